// round 6
// baseline (speedup 1.0000x reference)
#include <cuda_runtime.h>
#include <cuda_bf16.h>
#include <math.h>

typedef unsigned int uint;
typedef __nv_bfloat16 bf;

#define BB 2
#define SEQ 2048
#define EMB 1024
#define NH 16
#define DH 64
#define MTOT (BB * SEQ)          // 4096

// 0.125 * log2(e)
#define QSCALE 0.18033688011112042f

// ---------------- bf16 hi/lo scratch planes ----------------
__device__ bf g_dech[MTOT * EMB], g_decl[MTOT * EMB];
__device__ bf g_ench[MTOT * EMB], g_encl[MTOT * EMB];
__device__ bf g_wqh[NH * EMB * DH], g_wql[NH * EMB * DH];
__device__ bf g_wkh[NH * EMB * DH], g_wkl[NH * EMB * DH];
__device__ bf g_wvh[NH * EMB * DH], g_wvl[NH * EMB * DH];
__device__ bf g_woh[EMB * EMB],    g_wol[EMB * EMB];
__device__ bf g_Qh[BB * NH * SEQ * DH], g_Ql[BB * NH * SEQ * DH];
__device__ bf g_Kh[BB * NH * SEQ * DH], g_Kl[BB * NH * SEQ * DH];
__device__ bf g_Vth[BB * NH * DH * SEQ], g_Vtl[BB * NH * DH * SEQ]; // [bh][d][key]
__device__ bf g_ctxh[MTOT * EMB], g_ctxl[MTOT * EMB];

// ---------------- helpers ----------------
__device__ __forceinline__ uint pack_bf16x2(float lo_elem, float hi_elem) {
    uint r;
    asm("cvt.rn.bf16x2.f32 %0, %1, %2;" : "=r"(r) : "f"(hi_elem), "f"(lo_elem));
    return r;
}
__device__ __forceinline__ void split_pair(float x0, float x1, uint& h, uint& l) {
    h = pack_bf16x2(x0, x1);
    float h0 = __uint_as_float(h << 16);
    float h1 = __uint_as_float(h & 0xffff0000u);
    l = pack_bf16x2(x0 - h0, x1 - h1);
}
__device__ __forceinline__ void split_scalar(float x, bf& h, bf& l) {
    h = __float2bfloat16_rn(x);
    l = __float2bfloat16_rn(x - __bfloat162float(h));
}
__device__ __forceinline__ float fast_ex2(float x) {
    float y; asm("ex2.approx.f32 %0, %1;" : "=f"(y) : "f"(x)); return y;
}

#define MMA_BF16(d, a0, a1, a2, a3, b0, b1)                                    \
    asm volatile(                                                              \
        "mma.sync.aligned.m16n8k16.row.col.f32.bf16.bf16.f32 "                 \
        "{%0,%1,%2,%3}, {%4,%5,%6,%7}, {%8,%9}, {%0,%1,%2,%3};"                \
        : "+f"(d[0]), "+f"(d[1]), "+f"(d[2]), "+f"(d[3])                       \
        : "r"(a0), "r"(a1), "r"(a2), "r"(a3), "r"(b0), "r"(b1))

#define LDSM4(r0, r1, r2, r3, addr)                                            \
    asm volatile("ldmatrix.sync.aligned.m8n8.x4.shared.b16 {%0,%1,%2,%3}, [%4];" \
        : "=r"(r0), "=r"(r1), "=r"(r2), "=r"(r3) : "r"(addr))

#define LDSM4T(r0, r1, r2, r3, addr)                                           \
    asm volatile("ldmatrix.sync.aligned.m8n8.x4.trans.shared.b16 {%0,%1,%2,%3}, [%4];" \
        : "=r"(r0), "=r"(r1), "=r"(r2), "=r"(r3) : "r"(addr))

__device__ __forceinline__ uint ldsw(const bf* p) { return *(const uint*)p; }

__device__ __forceinline__ void cp_async16(uint saddr, const void* gptr) {
    asm volatile("cp.async.cg.shared.global [%0], [%1], 16;" :: "r"(saddr), "l"(gptr));
}
#define CP_COMMIT() asm volatile("cp.async.commit_group;")
#define CP_WAIT1()  asm volatile("cp.async.wait_group 1;")

// ---------------- fused split kernels ----------------
__device__ __forceinline__ void split_body(const float* __restrict__ x,
    bf* __restrict__ h, bf* __restrict__ l, int n)
{
    int i = (blockIdx.x * 256 + threadIdx.x) * 2;
    if (i < n) {
        float2 v = *(const float2*)(x + i);
        uint hh, ll;
        split_pair(v.x, v.y, hh, ll);
        *(uint*)(h + i) = hh;
        *(uint*)(l + i) = ll;
    }
}

__global__ void __launch_bounds__(256) split_duo(
    const float* __restrict__ x0, bf* h0, bf* l0,
    const float* __restrict__ x1, bf* h1, bf* l1, int n)
{
    if (blockIdx.y == 0) split_body(x0, h0, l0, n);
    else                 split_body(x1, h1, l1, n);
}

__global__ void __launch_bounds__(256) split_quad(
    const float* __restrict__ x0, bf* h0, bf* l0,
    const float* __restrict__ x1, bf* h1, bf* l1,
    const float* __restrict__ x2, bf* h2, bf* l2,
    const float* __restrict__ x3, bf* h3, bf* l3, int n)
{
    switch (blockIdx.y) {
        case 0: split_body(x0, h0, l0, n); break;
        case 1: split_body(x1, h1, l1, n); break;
        case 2: split_body(x2, h2, l2, n); break;
        default: split_body(x3, h3, l3, n); break;
    }
}

// ---------------------------------------------------------------------------
// Pipelined split-3 GEMM core v2. Tiles: BM=128, BN=128, BK=32.
// A staged [m][k] stride SA; W staged [k][n] stride SB (LDSM4T for B frags).
// 2-stage cp.async ring. 8 warps (4m x 2n), per-warp 32m x 64n.
// ---------------------------------------------------------------------------
#define SA 40
#define SB 136                   // 128 + 8 pad; 8 k-rows hit distinct 16B banks
#define APL (128 * SA)           // 5120 elems / A plane
#define WPL (32 * SB)            // 4352 elems / W plane
#define STG (2 * APL + 2 * WPL)  // 18944 elems / stage
#define STGB (STG * 2)           // bytes / stage
#define GSMEM (2 * STGB)         // 75776 bytes

struct GemmCtx {
    const bf *aP0, *aP1;         // A cp.async base ptrs (i=0 hi, i=2 lo)
    uint aD0, aD1;               // smem byte dsts (stage 0)
    const bf *wP0, *wP1;         // W base ptrs (hi, lo)
    uint wD0, wD1;
    int w16;                     // 16*ldw source offset (elems)
    int wadv;                    // 32*ldw per-iter advance
    uint a_stat, b_stat;         // lane-static ldmatrix bases (stage 0)
};

// A-side + ldmatrix setup (shared). W sources filled by caller.
__device__ __forceinline__ void gemm_setup_a(GemmCtx& cx, uint sm_u32,
    int tid, int lane, const bf* Ah, const bf* Al, int m0)
{
    const int quad = tid & 3;            // constant across chunks
    const int row = (tid >> 2) & 63;     // i toggles +64
    cx.aP0 = Ah + (size_t)(m0 + row) * EMB + quad * 8;
    cx.aP1 = Al + (size_t)(m0 + row) * EMB + quad * 8;
    cx.aD0 = sm_u32 + (uint)((row * SA + quad * 8) * 2);
    cx.aD1 = cx.aD0 + (uint)(APL * 2);
    const uint rowpart = (uint)((lane & 7) + 8 * ((lane >> 3) & 1));
    cx.a_stat = sm_u32 + rowpart * (SA * 2) + (uint)((lane >> 4) * 16);
    cx.b_stat = sm_u32 + (uint)(2 * APL * 2) + rowpart * (SB * 2)
              + (uint)((lane >> 4) * (WPL * 2));
}

#define A64S (64 * EMB)          // A source +64 rows (elems)
#define A64D (64 * SA * 2)       // A dst +64 rows (bytes)
#define W16D (16 * SB * 2)       // W dst +16 k-rows (bytes)

__device__ __forceinline__ void gemm_prefetch(const GemmCtx& cx, int it)
{
    const uint so = (uint)((it & 1) * STGB);
    const int ka = it * 32;
    cp_async16(cx.aD0 + so,        cx.aP0 + ka);
    cp_async16(cx.aD0 + so + A64D, cx.aP0 + A64S + ka);
    cp_async16(cx.aD1 + so,        cx.aP1 + ka);
    cp_async16(cx.aD1 + so + A64D, cx.aP1 + A64S + ka);
    const int kw = it * cx.wadv;
    cp_async16(cx.wD0 + so,        cx.wP0 + kw);
    cp_async16(cx.wD0 + so + W16D, cx.wP0 + cx.w16 + kw);
    cp_async16(cx.wD1 + so,        cx.wP1 + kw);
    cp_async16(cx.wD1 + so + W16D, cx.wP1 + cx.w16 + kw);
}

__device__ __forceinline__ void gemm_mainloop(GemmCtx& cx, float acc[2][8][4],
                                              int wm, int wn)
{
#pragma unroll 1
    for (int it = 0; it < 32; it++) {
        if (it + 1 < 32) gemm_prefetch(cx, it + 1);
        CP_COMMIT();
        CP_WAIT1();
        __syncthreads();

        const uint so = (uint)((it & 1) * STGB);
#pragma unroll
        for (int ks = 0; ks < 2; ks++) {
            uint ah[2][4], al2[2][4];
#pragma unroll
            for (int i = 0; i < 2; i++) {
                const uint ab = cx.a_stat + so
                              + (uint)((wm * 32 + 16 * i) * SA * 2 + ks * 32);
                LDSM4(ah[i][0], ah[i][1], ah[i][2], ah[i][3], ab);
                LDSM4(al2[i][0], al2[i][1], al2[i][2], al2[i][3], ab + APL * 2);
            }
#pragma unroll
            for (int j = 0; j < 8; j++) {
                uint bh0, bh1, bl0, bl1;
                LDSM4T(bh0, bh1, bl0, bl1,
                       cx.b_stat + so + (uint)(ks * W16D + (wn * 64 + 8 * j) * 2));
#pragma unroll
                for (int i = 0; i < 2; i++) {
                    MMA_BF16(acc[i][j], ah[i][0], ah[i][1], ah[i][2], ah[i][3], bh0, bh1);
                    MMA_BF16(acc[i][j], ah[i][0], ah[i][1], ah[i][2], ah[i][3], bl0, bl1);
                    MMA_BF16(acc[i][j], al2[i][0], al2[i][1], al2[i][2], al2[i][3], bh0, bh1);
                }
            }
        }
        __syncthreads();
    }
}

// ---- fused QKV projection: grid (8 head-pairs, 32 m-blocks, 3) ----
__global__ void __launch_bounds__(256) qkv_gemm(
    const bf* __restrict__ dech, const bf* __restrict__ decl,
    const bf* __restrict__ ench, const bf* __restrict__ encl,
    const bf* __restrict__ wqh, const bf* __restrict__ wql,
    const bf* __restrict__ wkh, const bf* __restrict__ wkl,
    const bf* __restrict__ wvh, const bf* __restrict__ wvl,
    const float* __restrict__ bq, const float* __restrict__ bk,
    const float* __restrict__ bv,
    bf* __restrict__ Qh, bf* __restrict__ Ql,
    bf* __restrict__ Kh, bf* __restrict__ Kl,
    bf* __restrict__ Vth, bf* __restrict__ Vtl)
{
    extern __shared__ bf smg[];
    const int z = blockIdx.z;
    const int hp = blockIdx.x;           // head pair
    const int m0 = blockIdx.y * 128;
    const int tid = threadIdx.x;
    const int lane = tid & 31, wid = tid >> 5;
    const int wm = wid & 3, wn = wid >> 2;
    const int g = lane >> 2, tig = lane & 3;

    const bf *Ah, *Al, *Wh, *Wl;
    const float* bias;
    if (z == 0)      { Ah = dech; Al = decl; Wh = wqh; Wl = wql; bias = bq; }
    else if (z == 1) { Ah = ench; Al = encl; Wh = wkh; Wl = wkl; bias = bk; }
    else             { Ah = ench; Al = encl; Wh = wvh; Wl = wvl; bias = bv; }

    const uint sm_u32 = (uint)__cvta_generic_to_shared(smg);
    GemmCtx cx;
    gemm_setup_a(cx, sm_u32, tid, lane, Ah, Al, m0);
    // W sources: chunk = tid&15 covers cols chunk*8..+7 (one head each, 8|64)
    {
        const int chunk = tid & 15;
        const int krow = (tid >> 4) & 15;   // 0..15 (i toggles +16)
        const int head = hp * 2 + (chunk >> 3);
        const int d = (chunk & 7) * 8;
        const size_t wb = ((size_t)head * EMB + krow) * DH + d;
        cx.wP0 = Wh + wb;
        cx.wP1 = Wl + wb;
        cx.wD0 = sm_u32 + (uint)((2 * APL + krow * SB + chunk * 8) * 2);
        cx.wD1 = cx.wD0 + (uint)(WPL * 2);
        cx.w16 = 16 * DH;
        cx.wadv = 32 * DH;
    }
    gemm_prefetch(cx, 0);
    CP_COMMIT();

    float acc[2][8][4] = {};
    gemm_mainloop(cx, acc, wm, wn);

    // ----- epilogue -----
#pragma unroll
    for (int i = 0; i < 2; i++) {
        const int r0 = m0 + wm * 32 + 16 * i + g;
        const int r1 = r0 + 8;
#pragma unroll
        for (int j = 0; j < 8; j++) {
            const int c = wn * 64 + 8 * j + 2 * tig;      // 0..127
            const int head = hp * 2 + (c >> 6);
            const int d = c & 63;
            float v00 = acc[i][j][0] + bias[head * DH + d];
            float v01 = acc[i][j][1] + bias[head * DH + d + 1];
            float v10 = acc[i][j][2] + bias[head * DH + d];
            float v11 = acc[i][j][3] + bias[head * DH + d + 1];
            if (z == 0) { v00 *= QSCALE; v01 *= QSCALE; v10 *= QSCALE; v11 *= QSCALE; }

            const int b0_ = r0 >> 11, q0_ = r0 & 2047;
            const int b1_ = r1 >> 11, q1_ = r1 & 2047;
            if (z < 2) {
                bf *Oh = (z == 0) ? Qh : Kh, *Ol = (z == 0) ? Ql : Kl;
                uint h, l;
                size_t i0 = (((size_t)b0_ * NH + head) * SEQ + q0_) * DH + d;
                split_pair(v00, v01, h, l);
                *(uint*)(Oh + i0) = h; *(uint*)(Ol + i0) = l;
                size_t i1 = (((size_t)b1_ * NH + head) * SEQ + q1_) * DH + d;
                split_pair(v10, v11, h, l);
                *(uint*)(Oh + i1) = h; *(uint*)(Ol + i1) = l;
            } else {
                size_t base0 = (((size_t)b0_ * NH + head) * DH + d) * SEQ;
                size_t base1 = (((size_t)b1_ * NH + head) * DH + d) * SEQ;
                bf h, l;
                split_scalar(v00, h, l); Vth[base0 + q0_] = h; Vtl[base0 + q0_] = l;
                split_scalar(v01, h, l); Vth[base0 + SEQ + q0_] = h; Vtl[base0 + SEQ + q0_] = l;
                split_scalar(v10, h, l); Vth[base1 + q1_] = h; Vtl[base1 + q1_] = l;
                split_scalar(v11, h, l); Vth[base1 + SEQ + q1_] = h; Vtl[base1 + SEQ + q1_] = l;
            }
        }
    }
}

// ---- output projection: grid (8 n-blocks, 32 m-blocks) ----
__global__ void __launch_bounds__(256) wo_gemm(
    const bf* __restrict__ Ah, const bf* __restrict__ Al,
    const bf* __restrict__ Wh, const bf* __restrict__ Wl,
    const float* __restrict__ bias, float* __restrict__ Of)
{
    extern __shared__ bf smg[];
    const int n0 = blockIdx.x * 128;
    const int m0 = blockIdx.y * 128;
    const int tid = threadIdx.x;
    const int lane = tid & 31, wid = tid >> 5;
    const int wm = wid & 3, wn = wid >> 2;
    const int g = lane >> 2, tig = lane & 3;

    const uint sm_u32 = (uint)__cvta_generic_to_shared(smg);
    GemmCtx cx;
    gemm_setup_a(cx, sm_u32, tid, lane, Ah, Al, m0);
    {
        const int chunk = tid & 15;
        const int krow = (tid >> 4) & 15;
        const size_t wb = (size_t)krow * EMB + n0 + chunk * 8;
        cx.wP0 = Wh + wb;
        cx.wP1 = Wl + wb;
        cx.wD0 = sm_u32 + (uint)((2 * APL + krow * SB + chunk * 8) * 2);
        cx.wD1 = cx.wD0 + (uint)(WPL * 2);
        cx.w16 = 16 * EMB;
        cx.wadv = 32 * EMB;
    }
    gemm_prefetch(cx, 0);
    CP_COMMIT();

    float acc[2][8][4] = {};
    gemm_mainloop(cx, acc, wm, wn);

#pragma unroll
    for (int i = 0; i < 2; i++) {
        const int r0 = m0 + wm * 32 + 16 * i + g;
        const int r1 = r0 + 8;
#pragma unroll
        for (int j = 0; j < 8; j++) {
            const int c = n0 + wn * 64 + 8 * j + 2 * tig;
            Of[(size_t)r0 * EMB + c]     = acc[i][j][0] + bias[c];
            Of[(size_t)r0 * EMB + c + 1] = acc[i][j][1] + bias[c + 1];
            Of[(size_t)r1 * EMB + c]     = acc[i][j][2] + bias[c];
            Of[(size_t)r1 * EMB + c + 1] = acc[i][j][3] + bias[c + 1];
        }
    }
}

// ---------------------------------------------------------------------------
// Flash attention: batched softmax (all ex2+splits before PV MMA burst).
// ---------------------------------------------------------------------------
#define ST 72
#define PL (64 * ST)
#define BUFSZ (4 * PL)

__global__ void __launch_bounds__(256) attn_mma(
    const bf* __restrict__ Qh, const bf* __restrict__ Ql,
    const bf* __restrict__ Kh, const bf* __restrict__ Kl,
    const bf* __restrict__ Vth, const bf* __restrict__ Vtl,
    bf* __restrict__ Ch, bf* __restrict__ Cl)
{
    extern __shared__ bf sm[];   // 2 * BUFSZ

    const int bh = blockIdx.y;
    const int q0 = blockIdx.x * 128;
    const int tid = threadIdx.x;
    const int lane = tid & 31, wid = tid >> 5;
    const int g = lane >> 2, tig = lane & 3;

    const size_t qkbase = (size_t)bh * SEQ * DH;
    const uint sm_u32 = (uint)__cvta_generic_to_shared(sm);

    const uint fr_stat = (uint)((lane & 7) * (ST * 2))
                       + (uint)(((lane >> 3) & 1) * 16)
                       + (uint)((lane >> 4) * (PL * 2));
    const uint k_stat = sm_u32 + fr_stat;
    const uint v_stat = sm_u32 + fr_stat + 2 * PL * 2;

    const int p = tid >> 6, r = tid & 63;
    const bf* gsrc;
    int gadv;
    if (p == 0)      { gsrc = Kh  + qkbase + (size_t)r * DH;     gadv = 64 * DH; }
    else if (p == 1) { gsrc = Kl  + qkbase + (size_t)r * DH;     gadv = 64 * DH; }
    else if (p == 2) { gsrc = Vth + ((size_t)bh * DH + r) * SEQ; gadv = 64; }
    else             { gsrc = Vtl + ((size_t)bh * DH + r) * SEQ; gadv = 64; }
    const uint sdst0 = sm_u32 + (uint)(((size_t)p * PL + r * ST) * 2);

#pragma unroll
    for (int c = 0; c < 8; c++) cp_async16(sdst0 + c * 16, gsrc + c * 8);
    CP_COMMIT();
#pragma unroll
    for (int c = 0; c < 8; c++)
        cp_async16(sdst0 + BUFSZ * 2 + c * 16, gsrc + gadv + c * 8);
    CP_COMMIT();

    uint qfh[4][4], qfl[4][4];
    {
        const int row = q0 + wid * 16 + g;
        const bf* q0p = Qh + qkbase + (size_t)row * DH;
        const bf* q1p = q0p + 8 * DH;
        const bf* l0p = Ql + qkbase + (size_t)row * DH;
        const bf* l1p = l0p + 8 * DH;
#pragma unroll
        for (int kk = 0; kk < 4; kk++) {
            const int c = kk * 16 + 2 * tig;
            qfh[kk][0] = ldsw(q0p + c);     qfh[kk][1] = ldsw(q1p + c);
            qfh[kk][2] = ldsw(q0p + c + 8); qfh[kk][3] = ldsw(q1p + c + 8);
            qfl[kk][0] = ldsw(l0p + c);     qfl[kk][1] = ldsw(l1p + c);
            qfl[kk][2] = ldsw(l0p + c + 8); qfl[kk][3] = ldsw(l1p + c + 8);
        }
    }

    float l0 = 0.f, l1 = 0.f;
    float o[8][4] = {};

    for (int t = 0; t < 32; t++) {
        const uint bufoff = (uint)((t & 1) * (BUFSZ * 2));

        CP_WAIT1();
        __syncthreads();

        // ---- S = Q K^T ----
        float s[8][4] = {};
#pragma unroll
        for (int kk = 0; kk < 4; kk++) {
            const uint kb = k_stat + bufoff + (uint)(kk * 32);
#pragma unroll
            for (int j = 0; j < 8; j++) {
                uint bh0, bh1, bl0, bl1;
                LDSM4(bh0, bh1, bl0, bl1, kb + (uint)(j * (16 * ST)));
                MMA_BF16(s[j], qfh[kk][0], qfh[kk][1], qfh[kk][2], qfh[kk][3], bh0, bh1);
                MMA_BF16(s[j], qfh[kk][0], qfh[kk][1], qfh[kk][2], qfh[kk][3], bl0, bl1);
                MMA_BF16(s[j], qfl[kk][0], qfl[kk][1], qfl[kk][2], qfl[kk][3], bh0, bh1);
            }
        }

        // ---- batched softmax: all ex2 + splits first ----
        uint pa[4][4], pe[4][4];
#pragma unroll
        for (int kk = 0; kk < 4; kk++) {
            const int j0 = 2 * kk, j1 = 2 * kk + 1;
            float p00 = fast_ex2(s[j0][0]), p01 = fast_ex2(s[j0][1]);
            float p02 = fast_ex2(s[j0][2]), p03 = fast_ex2(s[j0][3]);
            float p10 = fast_ex2(s[j1][0]), p11 = fast_ex2(s[j1][1]);
            float p12 = fast_ex2(s[j1][2]), p13 = fast_ex2(s[j1][3]);
            l0 += p00 + p01 + p10 + p11;
            l1 += p02 + p03 + p12 + p13;
            split_pair(p00, p01, pa[kk][0], pe[kk][0]);
            split_pair(p02, p03, pa[kk][1], pe[kk][1]);
            split_pair(p10, p11, pa[kk][2], pe[kk][2]);
            split_pair(p12, p13, pa[kk][3], pe[kk][3]);
        }

        // ---- PV MMA burst ----
#pragma unroll
        for (int kk = 0; kk < 4; kk++) {
            const uint vb = v_stat + bufoff + (uint)(kk * 32);
#pragma unroll
            for (int j = 0; j < 8; j++) {
                uint bh0, bh1, bl0, bl1;
                LDSM4(bh0, bh1, bl0, bl1, vb + (uint)(j * (16 * ST)));
                MMA_BF16(o[j], pa[kk][0], pa[kk][1], pa[kk][2], pa[kk][3], bh0, bh1);
                MMA_BF16(o[j], pa[kk][0], pa[kk][1], pa[kk][2], pa[kk][3], bl0, bl1);
                MMA_BF16(o[j], pe[kk][0], pe[kk][1], pe[kk][2], pe[kk][3], bh0, bh1);
            }
        }

        __syncthreads();

        if (t + 2 < 32) {
            const uint sd = sdst0 + (uint)((t & 1) ? BUFSZ * 2 : 0);
            const bf* gs = gsrc + (size_t)(t + 2) * gadv;
#pragma unroll
            for (int c = 0; c < 8; c++) cp_async16(sd + c * 16, gs + c * 8);
        }
        CP_COMMIT();
    }

    l0 += __shfl_xor_sync(0xffffffffu, l0, 1);
    l0 += __shfl_xor_sync(0xffffffffu, l0, 2);
    l1 += __shfl_xor_sync(0xffffffffu, l1, 1);
    l1 += __shfl_xor_sync(0xffffffffu, l1, 2);
    const float inv0 = 1.0f / l0, inv1 = 1.0f / l1;

    const int b = bh >> 4, h = bh & 15;
    const int row0 = q0 + wid * 16 + g;
    const size_t m0g = (size_t)b * SEQ + row0;
    const size_t m1g = m0g + 8;
#pragma unroll
    for (int j = 0; j < 8; j++) {
        const int col = h * 64 + 8 * j + 2 * tig;
        uint hh, ll;
        split_pair(o[j][0] * inv0, o[j][1] * inv0, hh, ll);
        *(uint*)(Ch + m0g * EMB + col) = hh;
        *(uint*)(Cl + m0g * EMB + col) = ll;
        split_pair(o[j][2] * inv1, o[j][3] * inv1, hh, ll);
        *(uint*)(Ch + m1g * EMB + col) = hh;
        *(uint*)(Cl + m1g * EMB + col) = ll;
    }
}

// ---------------------------------------------------------------------------
extern "C" void kernel_launch(void* const* d_in, const int* in_sizes, int n_in,
                              void* d_out, int out_size)
{
    const float* dec = (const float*)d_in[0];
    const float* enc = (const float*)d_in[1];
    const float* wq  = (const float*)d_in[2];
    const float* bq  = (const float*)d_in[3];
    const float* wk  = (const float*)d_in[4];
    const float* bk  = (const float*)d_in[5];
    const float* wv  = (const float*)d_in[6];
    const float* bv  = (const float*)d_in[7];
    const float* wo  = (const float*)d_in[8];
    const float* bo  = (const float*)d_in[9];
    float* out = (float*)d_out;

    bf *dech, *decl, *ench, *encl;
    bf *wqh, *wql, *wkh, *wkl, *wvh, *wvl, *woh, *wol;
    bf *qh, *ql, *kh, *kl, *vth, *vtl, *ctxh, *ctxl;
    cudaGetSymbolAddress((void**)&dech, g_dech); cudaGetSymbolAddress((void**)&decl, g_decl);
    cudaGetSymbolAddress((void**)&ench, g_ench); cudaGetSymbolAddress((void**)&encl, g_encl);
    cudaGetSymbolAddress((void**)&wqh, g_wqh);   cudaGetSymbolAddress((void**)&wql, g_wql);
    cudaGetSymbolAddress((void**)&wkh, g_wkh);   cudaGetSymbolAddress((void**)&wkl, g_wkl);
    cudaGetSymbolAddress((void**)&wvh, g_wvh);   cudaGetSymbolAddress((void**)&wvl, g_wvl);
    cudaGetSymbolAddress((void**)&woh, g_woh);   cudaGetSymbolAddress((void**)&wol, g_wol);
    cudaGetSymbolAddress((void**)&qh, g_Qh);     cudaGetSymbolAddress((void**)&ql, g_Ql);
    cudaGetSymbolAddress((void**)&kh, g_Kh);     cudaGetSymbolAddress((void**)&kl, g_Kl);
    cudaGetSymbolAddress((void**)&vth, g_Vth);   cudaGetSymbolAddress((void**)&vtl, g_Vtl);
    cudaGetSymbolAddress((void**)&ctxh, g_ctxh); cudaGetSymbolAddress((void**)&ctxl, g_ctxl);

    const int smem_attn = 2 * BUFSZ * (int)sizeof(bf);   // 73728 B
    cudaFuncSetAttribute(attn_mma, cudaFuncAttributeMaxDynamicSharedMemorySize, smem_attn);
    cudaFuncSetAttribute(qkv_gemm, cudaFuncAttributeMaxDynamicSharedMemorySize, GSMEM);
    cudaFuncSetAttribute(wo_gemm,  cudaFuncAttributeMaxDynamicSharedMemorySize, GSMEM);

    // 1) split fp32 -> bf16 hi/lo
    const int nAct = MTOT * EMB;
    const int nW   = EMB * EMB;
    dim3 gduo(nAct / 512, 2);
    split_duo<<<gduo, 256>>>(dec, dech, decl, enc, ench, encl, nAct);
    dim3 gquad(nW / 512, 4);
    split_quad<<<gquad, 256>>>(wq, wqh, wql, wk, wkh, wkl,
                               wv, wvh, wvl, wo, woh, wol, nW);

    // 2) fused QKV projections (BN=128 spans 2 heads)
    dim3 gqkv(NH / 2, MTOT / 128, 3);
    qkv_gemm<<<gqkv, 256, GSMEM>>>(dech, decl, ench, encl,
                                   wqh, wql, wkh, wkl, wvh, wvl,
                                   bq, bk, bv,
                                   qh, ql, kh, kl, vth, vtl);

    // 3) attention
    dim3 gattn(SEQ / 128, BB * NH);
    attn_mma<<<gattn, 256, smem_attn>>>(qh, ql, kh, kl, vth, vtl, ctxh, ctxl);

    // 4) output projection (fp32 out)
    dim3 gwo(EMB / 128, MTOT / 128);
    wo_gemm<<<gwo, 256, GSMEM>>>(ctxh, ctxl, woh, wol, bo, out);
}

// round 7
// speedup vs baseline: 1.0339x; 1.0339x over previous
#include <cuda_runtime.h>
#include <cuda_bf16.h>
#include <math.h>

typedef unsigned int uint;
typedef __nv_bfloat16 bf;

#define BB 2
#define SEQ 2048
#define EMB 1024
#define NH 16
#define DH 64
#define MTOT (BB * SEQ)          // 4096

// 0.125 * log2(e)
#define QSCALE 0.18033688011112042f

// ---------------- bf16 hi/lo scratch planes ----------------
__device__ bf g_dech[MTOT * EMB], g_decl[MTOT * EMB];
__device__ bf g_ench[MTOT * EMB], g_encl[MTOT * EMB];
__device__ bf g_wqh[NH * EMB * DH], g_wql[NH * EMB * DH];
__device__ bf g_wkh[NH * EMB * DH], g_wkl[NH * EMB * DH];
__device__ bf g_wvh[NH * EMB * DH], g_wvl[NH * EMB * DH];
__device__ bf g_woh[EMB * EMB],    g_wol[EMB * EMB];
__device__ bf g_Qh[BB * NH * SEQ * DH], g_Ql[BB * NH * SEQ * DH];
__device__ bf g_Kh[BB * NH * SEQ * DH], g_Kl[BB * NH * SEQ * DH];
__device__ bf g_Vth[BB * NH * DH * SEQ], g_Vtl[BB * NH * DH * SEQ]; // [bh][d][key]
__device__ bf g_ctxh[MTOT * EMB], g_ctxl[MTOT * EMB];

// ---------------- helpers ----------------
__device__ __forceinline__ uint pack_bf16x2(float lo_elem, float hi_elem) {
    uint r;
    asm("cvt.rn.bf16x2.f32 %0, %1, %2;" : "=r"(r) : "f"(hi_elem), "f"(lo_elem));
    return r;
}
__device__ __forceinline__ void split_pair(float x0, float x1, uint& h, uint& l) {
    h = pack_bf16x2(x0, x1);
    float h0 = __uint_as_float(h << 16);
    float h1 = __uint_as_float(h & 0xffff0000u);
    l = pack_bf16x2(x0 - h0, x1 - h1);
}
__device__ __forceinline__ void split_scalar(float x, bf& h, bf& l) {
    h = __float2bfloat16_rn(x);
    l = __float2bfloat16_rn(x - __bfloat162float(h));
}
__device__ __forceinline__ float fast_ex2(float x) {
    float y; asm("ex2.approx.f32 %0, %1;" : "=f"(y) : "f"(x)); return y;
}

#define MMA_BF16(d, a0, a1, a2, a3, b0, b1)                                    \
    asm volatile(                                                              \
        "mma.sync.aligned.m16n8k16.row.col.f32.bf16.bf16.f32 "                 \
        "{%0,%1,%2,%3}, {%4,%5,%6,%7}, {%8,%9}, {%0,%1,%2,%3};"                \
        : "+f"(d[0]), "+f"(d[1]), "+f"(d[2]), "+f"(d[3])                       \
        : "r"(a0), "r"(a1), "r"(a2), "r"(a3), "r"(b0), "r"(b1))

#define LDSM4(r0, r1, r2, r3, addr)                                            \
    asm volatile("ldmatrix.sync.aligned.m8n8.x4.shared.b16 {%0,%1,%2,%3}, [%4];" \
        : "=r"(r0), "=r"(r1), "=r"(r2), "=r"(r3) : "r"(addr))

#define LDSM4T(r0, r1, r2, r3, addr)                                           \
    asm volatile("ldmatrix.sync.aligned.m8n8.x4.trans.shared.b16 {%0,%1,%2,%3}, [%4];" \
        : "=r"(r0), "=r"(r1), "=r"(r2), "=r"(r3) : "r"(addr))

__device__ __forceinline__ uint ldsw(const bf* p) { return *(const uint*)p; }

__device__ __forceinline__ void cp_async16(uint saddr, const void* gptr) {
    asm volatile("cp.async.cg.shared.global [%0], [%1], 16;" :: "r"(saddr), "l"(gptr));
}
#define CP_COMMIT() asm volatile("cp.async.commit_group;")
#define CP_WAIT1()  asm volatile("cp.async.wait_group 1;")
#define CP_WAIT2()  asm volatile("cp.async.wait_group 2;")

// ---------------- fused split kernels ----------------
__device__ __forceinline__ void split_body(const float* __restrict__ x,
    bf* __restrict__ h, bf* __restrict__ l, int n)
{
    int i = (blockIdx.x * 256 + threadIdx.x) * 2;
    if (i < n) {
        float2 v = *(const float2*)(x + i);
        uint hh, ll;
        split_pair(v.x, v.y, hh, ll);
        *(uint*)(h + i) = hh;
        *(uint*)(l + i) = ll;
    }
}

__global__ void __launch_bounds__(256) split_duo(
    const float* __restrict__ x0, bf* h0, bf* l0,
    const float* __restrict__ x1, bf* h1, bf* l1, int n)
{
    if (blockIdx.y == 0) split_body(x0, h0, l0, n);
    else                 split_body(x1, h1, l1, n);
}

__global__ void __launch_bounds__(256) split_quad(
    const float* __restrict__ x0, bf* h0, bf* l0,
    const float* __restrict__ x1, bf* h1, bf* l1,
    const float* __restrict__ x2, bf* h2, bf* l2,
    const float* __restrict__ x3, bf* h3, bf* l3, int n)
{
    switch (blockIdx.y) {
        case 0: split_body(x0, h0, l0, n); break;
        case 1: split_body(x1, h1, l1, n); break;
        case 2: split_body(x2, h2, l2, n); break;
        default: split_body(x3, h3, l3, n); break;
    }
}

// ---------------------------------------------------------------------------
// Pipelined split-3 GEMM core (round-5 tiles, 3-stage ring).
// Tiles: BM=128, BN=64, BK=32. A [m][k] stride SA; W [k][n] stride SB (LDSM4T).
// 3-stage cp.async ring, wait_group 2 (2-tile lookahead).
// 8 warps (4m x 2n), per-warp 32m x 32n.
// ---------------------------------------------------------------------------
#define SA 40
#define SB 72
#define APL (128 * SA)           // 5120 elems per A plane
#define WPL (32 * SB)            // 2304 elems per W plane
#define STG (2 * APL + 2 * WPL)  // 14848 elems per stage
#define STGB (STG * 2)           // 29696 bytes per stage
#define GSMEM (3 * STGB)         // 89088 bytes

struct GemmCtx {
    const bf *asrc[4];           // per-thread A cp.async sources (k0=0)
    uint adst[4];                // smem byte offsets (stage 0)
    const bf *wsrc[2];
    uint wdst[2];
    int wadv;                    // W element advance per k-iter
    uint a_stat, b_stat;         // ldmatrix lane-static base addrs (stage 0)
};

__device__ __forceinline__ void gemm_prefetch(const GemmCtx& cx, int it)
{
    const uint so = (uint)((it % 3) * STGB);
    const int ka = it * 32;
#pragma unroll
    for (int i = 0; i < 4; i++)
        cp_async16(cx.adst[i] + so, cx.asrc[i] + ka);
#pragma unroll
    for (int i = 0; i < 2; i++)
        cp_async16(cx.wdst[i] + so, cx.wsrc[i] + it * cx.wadv);
}

__device__ __forceinline__ void gemm_mainloop(GemmCtx& cx, float acc[2][4][4],
                                              int wm, int wn)
{
#pragma unroll 1
    for (int it = 0; it < 32; it++) {
        if (it + 2 < 32) gemm_prefetch(cx, it + 2);
        CP_COMMIT();
        CP_WAIT2();
        __syncthreads();

        const uint so = (uint)((it % 3) * STGB);
#pragma unroll
        for (int ks = 0; ks < 2; ks++) {
            uint ah[2][4], al2[2][4];
#pragma unroll
            for (int i = 0; i < 2; i++) {
                const uint ab = cx.a_stat + so
                              + (uint)((wm * 32 + 16 * i) * SA * 2 + ks * 32);
                LDSM4(ah[i][0], ah[i][1], ah[i][2], ah[i][3], ab);
                LDSM4(al2[i][0], al2[i][1], al2[i][2], al2[i][3], ab + APL * 2);
            }
#pragma unroll
            for (int j = 0; j < 4; j++) {
                uint bh0, bh1, bl0, bl1;
                LDSM4T(bh0, bh1, bl0, bl1,
                       cx.b_stat + so + (uint)(ks * 16 * SB * 2 + (wn * 32 + 8 * j) * 2));
#pragma unroll
                for (int i = 0; i < 2; i++) {
                    MMA_BF16(acc[i][j], ah[i][0], ah[i][1], ah[i][2], ah[i][3], bh0, bh1);
                    MMA_BF16(acc[i][j], ah[i][0], ah[i][1], ah[i][2], ah[i][3], bl0, bl1);
                    MMA_BF16(acc[i][j], al2[i][0], al2[i][1], al2[i][2], al2[i][3], bh0, bh1);
                }
            }
        }
        __syncthreads();
    }
}

__device__ __forceinline__ void gemm_setup(GemmCtx& cx, uint sm_u32, int tid, int lane,
    const bf* Ah, const bf* Al, int m0,
    const bf* Wh, const bf* Wl, size_t wbase, int ldw, int noff)
{
    // A: 4 chunks of 16B per thread per iter
#pragma unroll
    for (int i = 0; i < 4; i++) {
        int c = i * 256 + tid;
        int quad = c & 3, row = (c >> 2) & 127, plane = (c >> 9) & 1;
        cx.asrc[i] = (plane ? Al : Ah) + (size_t)(m0 + row) * EMB + quad * 8;
        cx.adst[i] = sm_u32 + (uint)((plane * APL + row * SA + quad * 8) * 2);
    }
    // W: 2 chunks per thread per iter; staged [k][n]
#pragma unroll
    for (int i = 0; i < 2; i++) {
        int c = i * 256 + tid;
        int chunk = c & 7, krow = (c >> 3) & 31, plane = (c >> 8) & 1;
        cx.wsrc[i] = (plane ? Wl : Wh) + (wbase + krow) * (size_t)ldw + noff + chunk * 8;
        cx.wdst[i] = sm_u32 + (uint)((2 * APL + plane * WPL + krow * SB + chunk * 8) * 2);
    }
    cx.wadv = 32 * ldw;
    // lane-static ldmatrix addresses
    const uint rowpart = (uint)(((lane & 7) + 8 * ((lane >> 3) & 1)));
    cx.a_stat = sm_u32 + rowpart * (SA * 2) + (uint)((lane >> 4) * 16);
    cx.b_stat = sm_u32 + (uint)(2 * APL * 2) + rowpart * (SB * 2)
              + (uint)((lane >> 4) * (WPL * 2));
    // prologue: stages 0 and 1
    gemm_prefetch(cx, 0);
    CP_COMMIT();
    gemm_prefetch(cx, 1);
    CP_COMMIT();
}

// ---- fused QKV projection: grid (16 heads, 32 m-blocks, 3) ----
__global__ void __launch_bounds__(256) qkv_gemm(
    const bf* __restrict__ dech, const bf* __restrict__ decl,
    const bf* __restrict__ ench, const bf* __restrict__ encl,
    const bf* __restrict__ wqh, const bf* __restrict__ wql,
    const bf* __restrict__ wkh, const bf* __restrict__ wkl,
    const bf* __restrict__ wvh, const bf* __restrict__ wvl,
    const float* __restrict__ bq, const float* __restrict__ bk,
    const float* __restrict__ bv,
    bf* __restrict__ Qh, bf* __restrict__ Ql,
    bf* __restrict__ Kh, bf* __restrict__ Kl,
    bf* __restrict__ Vth, bf* __restrict__ Vtl)
{
    extern __shared__ bf smg[];
    const int z = blockIdx.z;
    const int head = blockIdx.x;
    const int m0 = blockIdx.y * 128;
    const int tid = threadIdx.x;
    const int lane = tid & 31, wid = tid >> 5;
    const int wm = wid & 3, wn = wid >> 2;
    const int g = lane >> 2, tig = lane & 3;

    const bf *Ah, *Al, *Wh, *Wl;
    const float* bias;
    if (z == 0)      { Ah = dech; Al = decl; Wh = wqh; Wl = wql; bias = bq; }
    else if (z == 1) { Ah = ench; Al = encl; Wh = wkh; Wl = wkl; bias = bk; }
    else             { Ah = ench; Al = encl; Wh = wvh; Wl = wvl; bias = bv; }

    GemmCtx cx;
    gemm_setup(cx, (uint)__cvta_generic_to_shared(smg), tid, lane,
               Ah, Al, m0, Wh, Wl, (size_t)head * EMB, DH, 0);

    float acc[2][4][4] = {};
    gemm_mainloop(cx, acc, wm, wn);

    // ----- epilogue -----
#pragma unroll
    for (int i = 0; i < 2; i++) {
        const int r0 = m0 + wm * 32 + 16 * i + g;
        const int r1 = r0 + 8;
#pragma unroll
        for (int j = 0; j < 4; j++) {
            const int d = wn * 32 + 8 * j + 2 * tig;   // 0..63 within head
            float v00 = acc[i][j][0] + bias[head * DH + d];
            float v01 = acc[i][j][1] + bias[head * DH + d + 1];
            float v10 = acc[i][j][2] + bias[head * DH + d];
            float v11 = acc[i][j][3] + bias[head * DH + d + 1];
            if (z == 0) { v00 *= QSCALE; v01 *= QSCALE; v10 *= QSCALE; v11 *= QSCALE; }

            const int b0_ = r0 >> 11, q0_ = r0 & 2047;
            const int b1_ = r1 >> 11, q1_ = r1 & 2047;
            if (z < 2) {
                bf *Oh = (z == 0) ? Qh : Kh, *Ol = (z == 0) ? Ql : Kl;
                uint h, l;
                size_t i0 = (((size_t)b0_ * NH + head) * SEQ + q0_) * DH + d;
                split_pair(v00, v01, h, l);
                *(uint*)(Oh + i0) = h; *(uint*)(Ol + i0) = l;
                size_t i1 = (((size_t)b1_ * NH + head) * SEQ + q1_) * DH + d;
                split_pair(v10, v11, h, l);
                *(uint*)(Oh + i1) = h; *(uint*)(Ol + i1) = l;
            } else {
                size_t base0 = (((size_t)b0_ * NH + head) * DH + d) * SEQ;
                size_t base1 = (((size_t)b1_ * NH + head) * DH + d) * SEQ;
                bf h, l;
                split_scalar(v00, h, l); Vth[base0 + q0_] = h; Vtl[base0 + q0_] = l;
                split_scalar(v01, h, l); Vth[base0 + SEQ + q0_] = h; Vtl[base0 + SEQ + q0_] = l;
                split_scalar(v10, h, l); Vth[base1 + q1_] = h; Vtl[base1 + q1_] = l;
                split_scalar(v11, h, l); Vth[base1 + SEQ + q1_] = h; Vtl[base1 + SEQ + q1_] = l;
            }
        }
    }
}

// ---- output projection: grid (16 n-blocks, 32 m-blocks) ----
__global__ void __launch_bounds__(256) wo_gemm(
    const bf* __restrict__ Ah, const bf* __restrict__ Al,
    const bf* __restrict__ Wh, const bf* __restrict__ Wl,
    const float* __restrict__ bias, float* __restrict__ Of)
{
    extern __shared__ bf smg[];
    const int n0 = blockIdx.x * 64;
    const int m0 = blockIdx.y * 128;
    const int tid = threadIdx.x;
    const int lane = tid & 31, wid = tid >> 5;
    const int wm = wid & 3, wn = wid >> 2;
    const int g = lane >> 2, tig = lane & 3;

    GemmCtx cx;
    gemm_setup(cx, (uint)__cvta_generic_to_shared(smg), tid, lane,
               Ah, Al, m0, Wh, Wl, 0, EMB, n0);

    float acc[2][4][4] = {};
    gemm_mainloop(cx, acc, wm, wn);

#pragma unroll
    for (int i = 0; i < 2; i++) {
        const int r0 = m0 + wm * 32 + 16 * i + g;
        const int r1 = r0 + 8;
#pragma unroll
        for (int j = 0; j < 4; j++) {
            const int c = n0 + wn * 32 + 8 * j + 2 * tig;
            Of[(size_t)r0 * EMB + c]     = acc[i][j][0] + bias[c];
            Of[(size_t)r0 * EMB + c + 1] = acc[i][j][1] + bias[c + 1];
            Of[(size_t)r1 * EMB + c]     = acc[i][j][2] + bias[c];
            Of[(size_t)r1 * EMB + c + 1] = acc[i][j][3] + bias[c + 1];
        }
    }
}

// ---------------------------------------------------------------------------
// Flash attention (round-5 version): Q frags in registers, cp.async
// double-buffered K/V, ldmatrix fragment loads, exp2-domain softmax
// interleaved with PV MMAs.
// ---------------------------------------------------------------------------
#define ST 72
#define PL (64 * ST)
#define BUFSZ (4 * PL)

__global__ void __launch_bounds__(256) attn_mma(
    const bf* __restrict__ Qh, const bf* __restrict__ Ql,
    const bf* __restrict__ Kh, const bf* __restrict__ Kl,
    const bf* __restrict__ Vth, const bf* __restrict__ Vtl,
    bf* __restrict__ Ch, bf* __restrict__ Cl)
{
    extern __shared__ bf sm[];   // 2 * BUFSZ

    const int bh = blockIdx.y;
    const int q0 = blockIdx.x * 128;
    const int tid = threadIdx.x;
    const int lane = tid & 31, wid = tid >> 5;
    const int g = lane >> 2, tig = lane & 3;

    const size_t qkbase = (size_t)bh * SEQ * DH;
    const uint sm_u32 = (uint)__cvta_generic_to_shared(sm);

    const uint fr_stat = (uint)((lane & 7) * (ST * 2))
                       + (uint)(((lane >> 3) & 1) * 16)
                       + (uint)((lane >> 4) * (PL * 2));
    const uint k_stat = sm_u32 + fr_stat;
    const uint v_stat = sm_u32 + fr_stat + 2 * PL * 2;

    const int p = tid >> 6, r = tid & 63;
    const bf* gsrc;
    int gadv;
    if (p == 0)      { gsrc = Kh  + qkbase + (size_t)r * DH;     gadv = 64 * DH; }
    else if (p == 1) { gsrc = Kl  + qkbase + (size_t)r * DH;     gadv = 64 * DH; }
    else if (p == 2) { gsrc = Vth + ((size_t)bh * DH + r) * SEQ; gadv = 64; }
    else             { gsrc = Vtl + ((size_t)bh * DH + r) * SEQ; gadv = 64; }
    const uint sdst0 = sm_u32 + (uint)(((size_t)p * PL + r * ST) * 2);

#pragma unroll
    for (int c = 0; c < 8; c++) cp_async16(sdst0 + c * 16, gsrc + c * 8);
    CP_COMMIT();
#pragma unroll
    for (int c = 0; c < 8; c++)
        cp_async16(sdst0 + BUFSZ * 2 + c * 16, gsrc + gadv + c * 8);
    CP_COMMIT();

    uint qfh[4][4], qfl[4][4];
    {
        const int row = q0 + wid * 16 + g;
        const bf* q0p = Qh + qkbase + (size_t)row * DH;
        const bf* q1p = q0p + 8 * DH;
        const bf* l0p = Ql + qkbase + (size_t)row * DH;
        const bf* l1p = l0p + 8 * DH;
#pragma unroll
        for (int kk = 0; kk < 4; kk++) {
            const int c = kk * 16 + 2 * tig;
            qfh[kk][0] = ldsw(q0p + c);     qfh[kk][1] = ldsw(q1p + c);
            qfh[kk][2] = ldsw(q0p + c + 8); qfh[kk][3] = ldsw(q1p + c + 8);
            qfl[kk][0] = ldsw(l0p + c);     qfl[kk][1] = ldsw(l1p + c);
            qfl[kk][2] = ldsw(l0p + c + 8); qfl[kk][3] = ldsw(l1p + c + 8);
        }
    }

    float l0 = 0.f, l1 = 0.f;
    float o[8][4] = {};

    for (int t = 0; t < 32; t++) {
        const uint bufoff = (uint)((t & 1) * (BUFSZ * 2));

        CP_WAIT1();
        __syncthreads();

        float s[8][4] = {};
#pragma unroll
        for (int kk = 0; kk < 4; kk++) {
            const uint kb = k_stat + bufoff + (uint)(kk * 32);
#pragma unroll
            for (int j = 0; j < 8; j++) {
                uint bh0, bh1, bl0, bl1;
                LDSM4(bh0, bh1, bl0, bl1, kb + (uint)(j * (16 * ST)));
                MMA_BF16(s[j], qfh[kk][0], qfh[kk][1], qfh[kk][2], qfh[kk][3], bh0, bh1);
                MMA_BF16(s[j], qfh[kk][0], qfh[kk][1], qfh[kk][2], qfh[kk][3], bl0, bl1);
                MMA_BF16(s[j], qfl[kk][0], qfl[kk][1], qfl[kk][2], qfl[kk][3], bh0, bh1);
            }
        }

#pragma unroll
        for (int kk = 0; kk < 4; kk++) {
            const int j0 = 2 * kk, j1 = 2 * kk + 1;
            float p00 = fast_ex2(s[j0][0]), p01 = fast_ex2(s[j0][1]);
            float p02 = fast_ex2(s[j0][2]), p03 = fast_ex2(s[j0][3]);
            float p10 = fast_ex2(s[j1][0]), p11 = fast_ex2(s[j1][1]);
            float p12 = fast_ex2(s[j1][2]), p13 = fast_ex2(s[j1][3]);
            l0 += p00 + p01 + p10 + p11;
            l1 += p02 + p03 + p12 + p13;
            uint a0, a1, a2, a3, e0, e1, e2, e3;
            split_pair(p00, p01, a0, e0);
            split_pair(p02, p03, a1, e1);
            split_pair(p10, p11, a2, e2);
            split_pair(p12, p13, a3, e3);
            const uint vb = v_stat + bufoff + (uint)(kk * 32);
#pragma unroll
            for (int j = 0; j < 8; j++) {
                uint bh0, bh1, bl0, bl1;
                LDSM4(bh0, bh1, bl0, bl1, vb + (uint)(j * (16 * ST)));
                MMA_BF16(o[j], a0, a1, a2, a3, bh0, bh1);
                MMA_BF16(o[j], a0, a1, a2, a3, bl0, bl1);
                MMA_BF16(o[j], e0, e1, e2, e3, bh0, bh1);
            }
        }

        __syncthreads();

        if (t + 2 < 32) {
            const uint sd = sdst0 + (uint)((t & 1) ? BUFSZ * 2 : 0);
            const bf* gs = gsrc + (size_t)(t + 2) * gadv;
#pragma unroll
            for (int c = 0; c < 8; c++) cp_async16(sd + c * 16, gs + c * 8);
        }
        CP_COMMIT();
    }

    l0 += __shfl_xor_sync(0xffffffffu, l0, 1);
    l0 += __shfl_xor_sync(0xffffffffu, l0, 2);
    l1 += __shfl_xor_sync(0xffffffffu, l1, 1);
    l1 += __shfl_xor_sync(0xffffffffu, l1, 2);
    const float inv0 = 1.0f / l0, inv1 = 1.0f / l1;

    const int b = bh >> 4, h = bh & 15;
    const int row0 = q0 + wid * 16 + g;
    const size_t m0g = (size_t)b * SEQ + row0;
    const size_t m1g = m0g + 8;
#pragma unroll
    for (int j = 0; j < 8; j++) {
        const int col = h * 64 + 8 * j + 2 * tig;
        uint hh, ll;
        split_pair(o[j][0] * inv0, o[j][1] * inv0, hh, ll);
        *(uint*)(Ch + m0g * EMB + col) = hh;
        *(uint*)(Cl + m0g * EMB + col) = ll;
        split_pair(o[j][2] * inv1, o[j][3] * inv1, hh, ll);
        *(uint*)(Ch + m1g * EMB + col) = hh;
        *(uint*)(Cl + m1g * EMB + col) = ll;
    }
}

// ---------------------------------------------------------------------------
extern "C" void kernel_launch(void* const* d_in, const int* in_sizes, int n_in,
                              void* d_out, int out_size)
{
    const float* dec = (const float*)d_in[0];
    const float* enc = (const float*)d_in[1];
    const float* wq  = (const float*)d_in[2];
    const float* bq  = (const float*)d_in[3];
    const float* wk  = (const float*)d_in[4];
    const float* bk  = (const float*)d_in[5];
    const float* wv  = (const float*)d_in[6];
    const float* bv  = (const float*)d_in[7];
    const float* wo  = (const float*)d_in[8];
    const float* bo  = (const float*)d_in[9];
    float* out = (float*)d_out;

    bf *dech, *decl, *ench, *encl;
    bf *wqh, *wql, *wkh, *wkl, *wvh, *wvl, *woh, *wol;
    bf *qh, *ql, *kh, *kl, *vth, *vtl, *ctxh, *ctxl;
    cudaGetSymbolAddress((void**)&dech, g_dech); cudaGetSymbolAddress((void**)&decl, g_decl);
    cudaGetSymbolAddress((void**)&ench, g_ench); cudaGetSymbolAddress((void**)&encl, g_encl);
    cudaGetSymbolAddress((void**)&wqh, g_wqh);   cudaGetSymbolAddress((void**)&wql, g_wql);
    cudaGetSymbolAddress((void**)&wkh, g_wkh);   cudaGetSymbolAddress((void**)&wkl, g_wkl);
    cudaGetSymbolAddress((void**)&wvh, g_wvh);   cudaGetSymbolAddress((void**)&wvl, g_wvl);
    cudaGetSymbolAddress((void**)&woh, g_woh);   cudaGetSymbolAddress((void**)&wol, g_wol);
    cudaGetSymbolAddress((void**)&qh, g_Qh);     cudaGetSymbolAddress((void**)&ql, g_Ql);
    cudaGetSymbolAddress((void**)&kh, g_Kh);     cudaGetSymbolAddress((void**)&kl, g_Kl);
    cudaGetSymbolAddress((void**)&vth, g_Vth);   cudaGetSymbolAddress((void**)&vtl, g_Vtl);
    cudaGetSymbolAddress((void**)&ctxh, g_ctxh); cudaGetSymbolAddress((void**)&ctxl, g_ctxl);

    const int smem_attn = 2 * BUFSZ * (int)sizeof(bf);   // 73728 B
    cudaFuncSetAttribute(attn_mma, cudaFuncAttributeMaxDynamicSharedMemorySize, smem_attn);
    cudaFuncSetAttribute(qkv_gemm, cudaFuncAttributeMaxDynamicSharedMemorySize, GSMEM);
    cudaFuncSetAttribute(wo_gemm,  cudaFuncAttributeMaxDynamicSharedMemorySize, GSMEM);

    // 1) split fp32 -> bf16 hi/lo
    const int nAct = MTOT * EMB;
    const int nW   = EMB * EMB;
    dim3 gduo(nAct / 512, 2);
    split_duo<<<gduo, 256>>>(dec, dech, decl, enc, ench, encl, nAct);
    dim3 gquad(nW / 512, 4);
    split_quad<<<gquad, 256>>>(wq, wqh, wql, wk, wkh, wkl,
                               wv, wvh, wvl, wo, woh, wol, nW);

    // 2) fused QKV projections
    dim3 gqkv(NH, MTOT / 128, 3);
    qkv_gemm<<<gqkv, 256, GSMEM>>>(dech, decl, ench, encl,
                                   wqh, wql, wkh, wkl, wvh, wvl,
                                   bq, bk, bv,
                                   qh, ql, kh, kl, vth, vtl);

    // 3) attention
    dim3 gattn(SEQ / 128, BB * NH);
    attn_mma<<<gattn, 256, smem_attn>>>(qh, ql, kh, kl, vth, vtl, ctxh, ctxl);

    // 4) output projection (fp32 out)
    dim3 gwo(EMB / 64, MTOT / 128);
    wo_gemm<<<gwo, 256, GSMEM>>>(ctxh, ctxl, woh, wol, bo, out);
}

// round 10
// speedup vs baseline: 1.9648x; 1.9004x over previous
#include <cuda_runtime.h>
#include <cuda_fp16.h>
#include <math.h>

typedef unsigned int uint;
typedef __half hf;

#define BB 2
#define SEQ 2048
#define EMB 1024
#define NH 16
#define DH 64
#define MTOT (BB * SEQ)          // 4096

// 0.125 * log2(e)
#define QSCALE 0.18033688011112042f

// ---------------- fp16 scratch ----------------
__device__ hf g_dech[MTOT * EMB], g_decl[MTOT * EMB];   // activations split-2
__device__ hf g_ench[MTOT * EMB], g_encl[MTOT * EMB];
__device__ hf g_wq1[NH * EMB * DH];                     // weights single fp16
__device__ hf g_wk1[NH * EMB * DH];
__device__ hf g_wv1[NH * EMB * DH];
__device__ hf g_wo1[EMB * EMB];
__device__ hf g_Qf[BB * NH * SEQ * DH];                 // Q/K single fp16
__device__ hf g_Kf[BB * NH * SEQ * DH];
__device__ hf g_Vtf[BB * NH * DH * SEQ];                // V single, [bh][d][key]
__device__ hf g_ctxh[MTOT * EMB], g_ctxl[MTOT * EMB];   // ctx split-2

// ---------------- helpers ----------------
__device__ __forceinline__ uint pack_h2(float lo, float hi) {
    __half2 v = __floats2half2_rn(lo, hi);
    return *(uint*)&v;
}
__device__ __forceinline__ void split_pair_h(float x0, float x1, uint& h, uint& l) {
    __half2 hh = __floats2half2_rn(x0, x1);
    float2 f = __half22float2(hh);
    __half2 ll = __floats2half2_rn(x0 - f.x, x1 - f.y);
    h = *(uint*)&hh; l = *(uint*)&ll;
}
__device__ __forceinline__ float fast_ex2(float x) {
    float y; asm("ex2.approx.f32 %0, %1;" : "=f"(y) : "f"(x)); return y;
}

#define MMA_F16(d, a0, a1, a2, a3, b0, b1)                                     \
    asm volatile(                                                              \
        "mma.sync.aligned.m16n8k16.row.col.f32.f16.f16.f32 "                   \
        "{%0,%1,%2,%3}, {%4,%5,%6,%7}, {%8,%9}, {%0,%1,%2,%3};"                \
        : "+f"(d[0]), "+f"(d[1]), "+f"(d[2]), "+f"(d[3])                       \
        : "r"(a0), "r"(a1), "r"(a2), "r"(a3), "r"(b0), "r"(b1))

#define LDSM4(r0, r1, r2, r3, addr)                                            \
    asm volatile("ldmatrix.sync.aligned.m8n8.x4.shared.b16 {%0,%1,%2,%3}, [%4];" \
        : "=r"(r0), "=r"(r1), "=r"(r2), "=r"(r3) : "r"(addr))

#define LDSM4T(r0, r1, r2, r3, addr)                                           \
    asm volatile("ldmatrix.sync.aligned.m8n8.x4.trans.shared.b16 {%0,%1,%2,%3}, [%4];" \
        : "=r"(r0), "=r"(r1), "=r"(r2), "=r"(r3) : "r"(addr))

__device__ __forceinline__ void cp_async16(uint saddr, const void* gptr) {
    asm volatile("cp.async.cg.shared.global [%0], [%1], 16;" :: "r"(saddr), "l"(gptr));
}
#define CP_COMMIT() asm volatile("cp.async.commit_group;")
#define CP_WAIT1()  asm volatile("cp.async.wait_group 1;")

// ---------------- split / convert kernels ----------------
__device__ __forceinline__ void split_body(const float* __restrict__ x,
    hf* __restrict__ h, hf* __restrict__ l, int n)
{
    int i = (blockIdx.x * 256 + threadIdx.x) * 2;
    if (i < n) {
        float2 v = *(const float2*)(x + i);
        uint hh, ll;
        split_pair_h(v.x, v.y, hh, ll);
        *(uint*)(h + i) = hh;
        *(uint*)(l + i) = ll;
    }
}

__global__ void __launch_bounds__(256) split_duo(
    const float* __restrict__ x0, hf* h0, hf* l0,
    const float* __restrict__ x1, hf* h1, hf* l1, int n)
{
    if (blockIdx.y == 0) split_body(x0, h0, l0, n);
    else                 split_body(x1, h1, l1, n);
}

__device__ __forceinline__ void conv_body(const float* __restrict__ x,
    hf* __restrict__ y, int n)
{
    int i = (blockIdx.x * 256 + threadIdx.x) * 2;
    if (i < n) {
        float2 v = *(const float2*)(x + i);
        *(uint*)(y + i) = pack_h2(v.x, v.y);
    }
}

__global__ void __launch_bounds__(256) conv_quad(
    const float* __restrict__ x0, hf* y0, const float* __restrict__ x1, hf* y1,
    const float* __restrict__ x2, hf* y2, const float* __restrict__ x3, hf* y3, int n)
{
    switch (blockIdx.y) {
        case 0: conv_body(x0, y0, n); break;
        case 1: conv_body(x1, y1, n); break;
        case 2: conv_body(x2, y2, n); break;
        default: conv_body(x3, y3, n); break;
    }
}

// ---------------------------------------------------------------------------
// Pipelined GEMM: C = (Ah+Al) @ W1 + bias (2 MMA terms).
// Tiles BM=128 BN=64 BK=32; A [m][k] stride SA; W [k][n] stride SB (LDSM4T,
// j-pair loading: lanes 16-31 fetch the n+8 block). 2-stage cp.async ring.
// Prefetch of tile it+2 happens AFTER the consume barrier (same-buffer reuse).
// 8 warps (4m x 2n), per-warp 32m x 32n.
// ---------------------------------------------------------------------------
#define SA 40
#define SB 72
#define APL (128 * SA)           // 5120 el / A plane
#define WPL (32 * SB)            // 2304 el
#define STG (2 * APL + WPL)      // 12544 el / stage
#define STGB (STG * 2)           // 25088 B
#define GSMEM (2 * STGB)         // 50176 B

struct GemmCtx {
    const hf *asrc[4];
    uint adst[4];
    const hf *wsrc;
    uint wdst;
    int wadv;
    uint a_stat, b_stat;
};

__device__ __forceinline__ void gemm_prefetch(const GemmCtx& cx, int it)
{
    const uint so = (uint)((it & 1) * STGB);
    const int ka = it * 32;
#pragma unroll
    for (int i = 0; i < 4; i++)
        cp_async16(cx.adst[i] + so, cx.asrc[i] + ka);
    cp_async16(cx.wdst + so, cx.wsrc + it * cx.wadv);
}

__device__ __forceinline__ void gemm_setup(GemmCtx& cx, uint sm_u32, int tid, int lane,
    const hf* Ah, const hf* Al, int m0,
    const hf* W1, size_t wbase, int ldw, int noff)
{
#pragma unroll
    for (int i = 0; i < 4; i++) {
        int c = i * 256 + tid;
        int quad = c & 3, row = (c >> 2) & 127, plane = (c >> 9) & 1;
        cx.asrc[i] = (plane ? Al : Ah) + (size_t)(m0 + row) * EMB + quad * 8;
        cx.adst[i] = sm_u32 + (uint)((plane * APL + row * SA + quad * 8) * 2);
    }
    {
        int chunk = tid & 7, krow = tid >> 3;    // 32 k-rows x 8 chunks
        cx.wsrc = W1 + (wbase + krow) * (size_t)ldw + noff + chunk * 8;
        cx.wdst = sm_u32 + (uint)((2 * APL + krow * SB + chunk * 8) * 2);
    }
    cx.wadv = 32 * ldw;
    const uint rowpart = (uint)((lane & 7) + 8 * ((lane >> 3) & 1));
    cx.a_stat = sm_u32 + rowpart * (SA * 2) + (uint)((lane >> 4) * 16);
    // B: lanes 0-7 k0-7, 8-15 k8-15 (rows), lanes 16-31 same rows at n+8
    cx.b_stat = sm_u32 + (uint)(2 * APL * 2) + rowpart * (SB * 2)
              + (uint)((lane >> 4) * 16);
    gemm_prefetch(cx, 0);
    CP_COMMIT();
    gemm_prefetch(cx, 1);
    CP_COMMIT();
}

__device__ __forceinline__ void gemm_mainloop(GemmCtx& cx, float acc[2][4][4],
                                              int wm, int wn)
{
#pragma unroll 1
    for (int it = 0; it < 32; it++) {
        CP_WAIT1();              // tile it resident
        __syncthreads();

        const uint so = (uint)((it & 1) * STGB);
#pragma unroll
        for (int ks = 0; ks < 2; ks++) {
            uint ah[2][4], al[2][4];
#pragma unroll
            for (int i = 0; i < 2; i++) {
                const uint ab = cx.a_stat + so
                              + (uint)((wm * 32 + 16 * i) * SA * 2 + ks * 32);
                LDSM4(ah[i][0], ah[i][1], ah[i][2], ah[i][3], ab);
                LDSM4(al[i][0], al[i][1], al[i][2], al[i][3], ab + APL * 2);
            }
#pragma unroll
            for (int jp = 0; jp < 2; jp++) {
                uint r0, r1, r2, r3;
                LDSM4T(r0, r1, r2, r3,
                       cx.b_stat + so + (uint)(ks * 16 * SB * 2 + (wn * 32 + jp * 16) * 2));
#pragma unroll
                for (int i = 0; i < 2; i++) {
                    MMA_F16(acc[i][2 * jp],     ah[i][0], ah[i][1], ah[i][2], ah[i][3], r0, r1);
                    MMA_F16(acc[i][2 * jp],     al[i][0], al[i][1], al[i][2], al[i][3], r0, r1);
                    MMA_F16(acc[i][2 * jp + 1], ah[i][0], ah[i][1], ah[i][2], ah[i][3], r2, r3);
                    MMA_F16(acc[i][2 * jp + 1], al[i][0], al[i][1], al[i][2], al[i][3], r2, r3);
                }
            }
        }
        __syncthreads();         // all reads of buffer (it&1) done

        if (it + 2 < 32) gemm_prefetch(cx, it + 2);   // safe: buffer free now
        CP_COMMIT();
    }
}

// ---- fused QKV: grid (16 heads, 32 m-blocks, 3) ----
__global__ void __launch_bounds__(256) qkv_gemm(
    const hf* __restrict__ dech, const hf* __restrict__ decl,
    const hf* __restrict__ ench, const hf* __restrict__ encl,
    const hf* __restrict__ wq1, const hf* __restrict__ wk1,
    const hf* __restrict__ wv1,
    const float* __restrict__ bq, const float* __restrict__ bk,
    const float* __restrict__ bv,
    hf* __restrict__ Qf, hf* __restrict__ Kf, hf* __restrict__ Vtf)
{
    extern __shared__ hf smg[];
    const int z = blockIdx.z;
    const int head = blockIdx.x;
    const int m0 = blockIdx.y * 128;
    const int tid = threadIdx.x;
    const int lane = tid & 31, wid = tid >> 5;
    const int wm = wid & 3, wn = wid >> 2;
    const int g = lane >> 2, tig = lane & 3;

    const hf *Ah, *Al, *W1; const float* bias;
    if (z == 0)      { Ah = dech; Al = decl; W1 = wq1; bias = bq; }
    else if (z == 1) { Ah = ench; Al = encl; W1 = wk1; bias = bk; }
    else             { Ah = ench; Al = encl; W1 = wv1; bias = bv; }

    GemmCtx cx;
    gemm_setup(cx, (uint)__cvta_generic_to_shared(smg), tid, lane,
               Ah, Al, m0, W1, (size_t)head * EMB, DH, 0);

    float acc[2][4][4] = {};
    gemm_mainloop(cx, acc, wm, wn);

#pragma unroll
    for (int i = 0; i < 2; i++) {
        const int r0 = m0 + wm * 32 + 16 * i + g;
        const int r1 = r0 + 8;
#pragma unroll
        for (int j = 0; j < 4; j++) {
            const int d = wn * 32 + 8 * j + 2 * tig;
            float v00 = acc[i][j][0] + bias[head * DH + d];
            float v01 = acc[i][j][1] + bias[head * DH + d + 1];
            float v10 = acc[i][j][2] + bias[head * DH + d];
            float v11 = acc[i][j][3] + bias[head * DH + d + 1];
            if (z == 0) { v00 *= QSCALE; v01 *= QSCALE; v10 *= QSCALE; v11 *= QSCALE; }

            const int b0_ = r0 >> 11, q0_ = r0 & 2047;
            const int b1_ = r1 >> 11, q1_ = r1 & 2047;
            if (z < 2) {
                hf* O = z ? Kf : Qf;
                size_t i0 = (((size_t)b0_ * NH + head) * SEQ + q0_) * DH + d;
                *(uint*)(O + i0) = pack_h2(v00, v01);
                size_t i1 = (((size_t)b1_ * NH + head) * SEQ + q1_) * DH + d;
                *(uint*)(O + i1) = pack_h2(v10, v11);
            } else {
                size_t base0 = (((size_t)b0_ * NH + head) * DH + d) * SEQ;
                size_t base1 = (((size_t)b1_ * NH + head) * DH + d) * SEQ;
                Vtf[base0 + q0_]       = __float2half_rn(v00);
                Vtf[base0 + SEQ + q0_] = __float2half_rn(v01);
                Vtf[base1 + q1_]       = __float2half_rn(v10);
                Vtf[base1 + SEQ + q1_] = __float2half_rn(v11);
            }
        }
    }
}

// ---- output projection: grid (16 n-blocks, 32 m-blocks) ----
__global__ void __launch_bounds__(256) wo_gemm(
    const hf* __restrict__ Ah, const hf* __restrict__ Al,
    const hf* __restrict__ W1,
    const float* __restrict__ bias, float* __restrict__ Of)
{
    extern __shared__ hf smg[];
    const int n0 = blockIdx.x * 64;
    const int m0 = blockIdx.y * 128;
    const int tid = threadIdx.x;
    const int lane = tid & 31, wid = tid >> 5;
    const int wm = wid & 3, wn = wid >> 2;
    const int g = lane >> 2, tig = lane & 3;

    GemmCtx cx;
    gemm_setup(cx, (uint)__cvta_generic_to_shared(smg), tid, lane,
               Ah, Al, m0, W1, 0, EMB, n0);

    float acc[2][4][4] = {};
    gemm_mainloop(cx, acc, wm, wn);

#pragma unroll
    for (int i = 0; i < 2; i++) {
        const int r0 = m0 + wm * 32 + 16 * i + g;
        const int r1 = r0 + 8;
#pragma unroll
        for (int j = 0; j < 4; j++) {
            const int c = n0 + wn * 32 + 8 * j + 2 * tig;
            Of[(size_t)r0 * EMB + c]     = acc[i][j][0] + bias[c];
            Of[(size_t)r0 * EMB + c + 1] = acc[i][j][1] + bias[c + 1];
            Of[(size_t)r1 * EMB + c]     = acc[i][j][2] + bias[c];
            Of[(size_t)r1 * EMB + c + 1] = acc[i][j][3] + bias[c + 1];
        }
    }
}

// ---------------------------------------------------------------------------
// Flash attention, single fp16: Q in smem (LDSM per kk), K/V single plane
// double-buffered via cp.async, 64 MMA/warp/tile, exp2 softmax.
// Block = 128 q rows of one (b,h), 8 warps x 16 rows.
// ---------------------------------------------------------------------------
#define ST 72
#define QPLB (128 * ST * 2)      // 18432 B Q plane
#define KVPLB (64 * ST * 2)      // 9216 B per K/V plane
#define STAGEB (2 * KVPLB)       // 18432 B per stage
#define ASMEM (QPLB + 2 * STAGEB)  // 55296 B

__global__ void __launch_bounds__(256, 3) attn_mma(
    const hf* __restrict__ Qf, const hf* __restrict__ Kf,
    const hf* __restrict__ Vtf,
    hf* __restrict__ Ch, hf* __restrict__ Cl)
{
    extern __shared__ hf sm[];

    const int bh = blockIdx.y;
    const int q0 = blockIdx.x * 128;
    const int tid = threadIdx.x;
    const int lane = tid & 31, wid = tid >> 5;
    const int g = lane >> 2, tig = lane & 3;

    const size_t qkbase = (size_t)bh * SEQ * DH;
    const uint smb = (uint)__cvta_generic_to_shared(sm);

    // A-frag lane offset (Q)
    const uint a_off = (uint)(((lane & 7) + 8 * ((lane >> 3) & 1)) * (ST * 2))
                     + (uint)((lane >> 4) * 16);
    // B-frag j-pair lane offset (K/V): lanes 16-31 fetch rows n+8
    const uint b_off = (uint)(((lane & 7) + 8 * (lane >> 4)) * (ST * 2))
                     + (uint)(((lane >> 3) & 1) * 16);
    const uint q_stat = smb + a_off + (uint)(wid * 16 * ST * 2);
    const uint k_stat = smb + QPLB + b_off;
    const uint v_stat = k_stat + KVPLB;

    // ---- cp.async sources (per thread: 2 K + 2 V chunks per tile) ----
    const int krow = tid >> 3, kch = tid & 7;
    const hf* kp = Kf + qkbase + (size_t)krow * DH + kch * 8;
    const hf* vp = Vtf + ((size_t)bh * DH + krow) * SEQ + kch * 8;
    const uint kd = smb + QPLB + (uint)((krow * ST + kch * 8) * 2);
    const uint vd = kd + KVPLB;

    // ---- prologue: Q plane + tiles 0,1 ----
    {
        const hf* qs = Qf + qkbase + (size_t)(q0 + (tid >> 1)) * DH + (tid & 1) * 32;
        const uint qd = smb + (uint)(((tid >> 1) * ST + (tid & 1) * 32) * 2);
#pragma unroll
        for (int c = 0; c < 4; c++) cp_async16(qd + c * 16, qs + c * 8);
    }
    cp_async16(kd, kp);                       cp_async16(kd + 32 * ST * 2, kp + 32 * DH);
    cp_async16(vd, vp);                       cp_async16(vd + 32 * ST * 2, vp + 32 * SEQ);
    CP_COMMIT();
    cp_async16(kd + STAGEB, kp + 64 * DH);    cp_async16(kd + STAGEB + 32 * ST * 2, kp + 96 * DH);
    cp_async16(vd + STAGEB, vp + 64);         cp_async16(vd + STAGEB + 32 * ST * 2, vp + 64 + 32 * SEQ);
    CP_COMMIT();

    float l0 = 0.f, l1 = 0.f;
    float o[8][4] = {};

#pragma unroll 1
    for (int t = 0; t < 32; t++) {
        const uint so = (uint)((t & 1) * STAGEB);

        CP_WAIT1();
        __syncthreads();

        // ---- S = Q K^T ----
        float s[8][4] = {};
#pragma unroll
        for (int kk = 0; kk < 4; kk++) {
            uint qa0, qa1, qa2, qa3;
            LDSM4(qa0, qa1, qa2, qa3, q_stat + (uint)(kk * 32));
#pragma unroll
            for (int jp = 0; jp < 4; jp++) {
                uint r0, r1, r2, r3;
                LDSM4(r0, r1, r2, r3, k_stat + so + (uint)(jp * 16 * ST * 2 + kk * 32));
                MMA_F16(s[2 * jp],     qa0, qa1, qa2, qa3, r0, r1);
                MMA_F16(s[2 * jp + 1], qa0, qa1, qa2, qa3, r2, r3);
            }
        }

        // ---- softmax (exp2, no max-sub) + P@V ----
#pragma unroll
        for (int kk = 0; kk < 4; kk++) {
            const int j0 = 2 * kk, j1 = 2 * kk + 1;
            float p00 = fast_ex2(s[j0][0]), p01 = fast_ex2(s[j0][1]);
            float p02 = fast_ex2(s[j0][2]), p03 = fast_ex2(s[j0][3]);
            float p10 = fast_ex2(s[j1][0]), p11 = fast_ex2(s[j1][1]);
            float p12 = fast_ex2(s[j1][2]), p13 = fast_ex2(s[j1][3]);
            l0 += p00 + p01 + p10 + p11;
            l1 += p02 + p03 + p12 + p13;
            const uint pa0 = pack_h2(p00, p01);
            const uint pa1 = pack_h2(p02, p03);
            const uint pa2 = pack_h2(p10, p11);
            const uint pa3 = pack_h2(p12, p13);
#pragma unroll
            for (int jp = 0; jp < 4; jp++) {
                uint r0, r1, r2, r3;
                LDSM4(r0, r1, r2, r3, v_stat + so + (uint)(jp * 16 * ST * 2 + kk * 32));
                MMA_F16(o[2 * jp],     pa0, pa1, pa2, pa3, r0, r1);
                MMA_F16(o[2 * jp + 1], pa0, pa1, pa2, pa3, r2, r3);
            }
        }

        __syncthreads();

        // ---- prefetch tile t+2 into the buffer just freed ----
        if (t + 2 < 32) {
            const uint sd = (uint)((t & 1) * STAGEB);
            const hf* ks = kp + (size_t)(t + 2) * 64 * DH;
            const hf* vs = vp + (t + 2) * 64;
            cp_async16(kd + sd, ks);
            cp_async16(kd + sd + 32 * ST * 2, ks + 32 * DH);
            cp_async16(vd + sd, vs);
            cp_async16(vd + sd + 32 * ST * 2, vs + 32 * SEQ);
        }
        CP_COMMIT();
    }

    l0 += __shfl_xor_sync(0xffffffffu, l0, 1);
    l0 += __shfl_xor_sync(0xffffffffu, l0, 2);
    l1 += __shfl_xor_sync(0xffffffffu, l1, 1);
    l1 += __shfl_xor_sync(0xffffffffu, l1, 2);
    const float inv0 = 1.0f / l0, inv1 = 1.0f / l1;

    const int b = bh >> 4, h = bh & 15;
    const int row0 = q0 + wid * 16 + g;
    const size_t m0g = (size_t)b * SEQ + row0;
    const size_t m1g = m0g + 8;
#pragma unroll
    for (int j = 0; j < 8; j++) {
        const int col = h * 64 + 8 * j + 2 * tig;
        uint hh, ll;
        split_pair_h(o[j][0] * inv0, o[j][1] * inv0, hh, ll);
        *(uint*)(Ch + m0g * EMB + col) = hh;
        *(uint*)(Cl + m0g * EMB + col) = ll;
        split_pair_h(o[j][2] * inv1, o[j][3] * inv1, hh, ll);
        *(uint*)(Ch + m1g * EMB + col) = hh;
        *(uint*)(Cl + m1g * EMB + col) = ll;
    }
}

// ---------------------------------------------------------------------------
extern "C" void kernel_launch(void* const* d_in, const int* in_sizes, int n_in,
                              void* d_out, int out_size)
{
    const float* dec = (const float*)d_in[0];
    const float* enc = (const float*)d_in[1];
    const float* wq  = (const float*)d_in[2];
    const float* bq  = (const float*)d_in[3];
    const float* wk  = (const float*)d_in[4];
    const float* bk  = (const float*)d_in[5];
    const float* wv  = (const float*)d_in[6];
    const float* bv  = (const float*)d_in[7];
    const float* wo  = (const float*)d_in[8];
    const float* bo  = (const float*)d_in[9];
    float* out = (float*)d_out;

    hf *dech, *decl, *ench, *encl;
    hf *wq1, *wk1, *wv1, *wo1;
    hf *qf, *kf, *vtf, *ctxh, *ctxl;
    cudaGetSymbolAddress((void**)&dech, g_dech); cudaGetSymbolAddress((void**)&decl, g_decl);
    cudaGetSymbolAddress((void**)&ench, g_ench); cudaGetSymbolAddress((void**)&encl, g_encl);
    cudaGetSymbolAddress((void**)&wq1, g_wq1);   cudaGetSymbolAddress((void**)&wk1, g_wk1);
    cudaGetSymbolAddress((void**)&wv1, g_wv1);   cudaGetSymbolAddress((void**)&wo1, g_wo1);
    cudaGetSymbolAddress((void**)&qf, g_Qf);     cudaGetSymbolAddress((void**)&kf, g_Kf);
    cudaGetSymbolAddress((void**)&vtf, g_Vtf);
    cudaGetSymbolAddress((void**)&ctxh, g_ctxh); cudaGetSymbolAddress((void**)&ctxl, g_ctxl);

    cudaFuncSetAttribute(attn_mma, cudaFuncAttributeMaxDynamicSharedMemorySize, ASMEM);
    cudaFuncSetAttribute(qkv_gemm, cudaFuncAttributeMaxDynamicSharedMemorySize, GSMEM);
    cudaFuncSetAttribute(wo_gemm,  cudaFuncAttributeMaxDynamicSharedMemorySize, GSMEM);

    // 1) activations split-2 fp16; weights single fp16
    const int nAct = MTOT * EMB;
    const int nW   = EMB * EMB;
    dim3 gduo(nAct / 512, 2);
    split_duo<<<gduo, 256>>>(dec, dech, decl, enc, ench, encl, nAct);
    dim3 gquad(nW / 512, 4);
    conv_quad<<<gquad, 256>>>(wq, wq1, wk, wk1, wv, wv1, wo, wo1, nW);

    // 2) fused QKV projections
    dim3 gqkv(NH, MTOT / 128, 3);
    qkv_gemm<<<gqkv, 256, GSMEM>>>(dech, decl, ench, encl,
                                   wq1, wk1, wv1, bq, bk, bv,
                                   qf, kf, vtf);

    // 3) attention
    dim3 gattn(SEQ / 128, BB * NH);
    attn_mma<<<gattn, 256, ASMEM>>>(qf, kf, vtf, ctxh, ctxl);

    // 4) output projection (fp32 out)
    dim3 gwo(EMB / 64, MTOT / 128);
    wo_gemm<<<gwo, 256, GSMEM>>>(ctxh, ctxl, wo1, bo, out);
}

// round 11
// speedup vs baseline: 2.0675x; 1.0523x over previous
#include <cuda_runtime.h>
#include <cuda_fp16.h>
#include <math.h>

typedef unsigned int uint;
typedef __half hf;

#define BB 2
#define SEQ 2048
#define EMB 1024
#define NH 16
#define DH 64
#define MTOT (BB * SEQ)          // 4096

// 0.125 * log2(e)
#define QSCALE 0.18033688011112042f

// ---------------- fp16 scratch ----------------
__device__ hf g_dech[MTOT * EMB], g_decl[MTOT * EMB];   // activations split-2
__device__ hf g_ench[MTOT * EMB], g_encl[MTOT * EMB];
__device__ hf g_wq1[NH * EMB * DH];                     // weights single fp16
__device__ hf g_wk1[NH * EMB * DH];
__device__ hf g_wv1[NH * EMB * DH];
__device__ hf g_wo1[EMB * EMB];
__device__ hf g_Qf[BB * NH * SEQ * DH];                 // Q/K single fp16
__device__ hf g_Kf[BB * NH * SEQ * DH];
__device__ hf g_Vtf[BB * NH * DH * SEQ];                // V single, [bh][d][key]
__device__ hf g_ctxh[MTOT * EMB], g_ctxl[MTOT * EMB];   // ctx split-2

// ---------------- helpers ----------------
__device__ __forceinline__ uint pack_h2(float lo, float hi) {
    __half2 v = __floats2half2_rn(lo, hi);
    return *(uint*)&v;
}
__device__ __forceinline__ void split_pair_h(float x0, float x1, uint& h, uint& l) {
    __half2 hh = __floats2half2_rn(x0, x1);
    float2 f = __half22float2(hh);
    __half2 ll = __floats2half2_rn(x0 - f.x, x1 - f.y);
    h = *(uint*)&hh; l = *(uint*)&ll;
}
// half2 exp2 (MUFU.EX2 on packed fp16x2)
__device__ __forceinline__ uint ex2_h2(uint x) {
    uint y; asm("ex2.approx.f16x2 %0, %1;" : "=r"(y) : "r"(x)); return y;
}

#define MMA_F16(d, a0, a1, a2, a3, b0, b1)                                     \
    asm volatile(                                                              \
        "mma.sync.aligned.m16n8k16.row.col.f32.f16.f16.f32 "                   \
        "{%0,%1,%2,%3}, {%4,%5,%6,%7}, {%8,%9}, {%0,%1,%2,%3};"                \
        : "+f"(d[0]), "+f"(d[1]), "+f"(d[2]), "+f"(d[3])                       \
        : "r"(a0), "r"(a1), "r"(a2), "r"(a3), "r"(b0), "r"(b1))

#define LDSM4(r0, r1, r2, r3, addr)                                            \
    asm volatile("ldmatrix.sync.aligned.m8n8.x4.shared.b16 {%0,%1,%2,%3}, [%4];" \
        : "=r"(r0), "=r"(r1), "=r"(r2), "=r"(r3) : "r"(addr))

#define LDSM4T(r0, r1, r2, r3, addr)                                           \
    asm volatile("ldmatrix.sync.aligned.m8n8.x4.trans.shared.b16 {%0,%1,%2,%3}, [%4];" \
        : "=r"(r0), "=r"(r1), "=r"(r2), "=r"(r3) : "r"(addr))

__device__ __forceinline__ void cp_async16(uint saddr, const void* gptr) {
    asm volatile("cp.async.cg.shared.global [%0], [%1], 16;" :: "r"(saddr), "l"(gptr));
}
#define CP_COMMIT() asm volatile("cp.async.commit_group;")
#define CP_WAIT1()  asm volatile("cp.async.wait_group 1;")

// ---------------- split / convert kernels ----------------
__device__ __forceinline__ void split_body(const float* __restrict__ x,
    hf* __restrict__ h, hf* __restrict__ l, int n)
{
    int i = (blockIdx.x * 256 + threadIdx.x) * 2;
    if (i < n) {
        float2 v = *(const float2*)(x + i);
        uint hh, ll;
        split_pair_h(v.x, v.y, hh, ll);
        *(uint*)(h + i) = hh;
        *(uint*)(l + i) = ll;
    }
}

__global__ void __launch_bounds__(256) split_duo(
    const float* __restrict__ x0, hf* h0, hf* l0,
    const float* __restrict__ x1, hf* h1, hf* l1, int n)
{
    if (blockIdx.y == 0) split_body(x0, h0, l0, n);
    else                 split_body(x1, h1, l1, n);
}

__device__ __forceinline__ void conv_body(const float* __restrict__ x,
    hf* __restrict__ y, int n)
{
    int i = (blockIdx.x * 256 + threadIdx.x) * 2;
    if (i < n) {
        float2 v = *(const float2*)(x + i);
        *(uint*)(y + i) = pack_h2(v.x, v.y);
    }
}

__global__ void __launch_bounds__(256) conv_quad(
    const float* __restrict__ x0, hf* y0, const float* __restrict__ x1, hf* y1,
    const float* __restrict__ x2, hf* y2, const float* __restrict__ x3, hf* y3, int n)
{
    switch (blockIdx.y) {
        case 0: conv_body(x0, y0, n); break;
        case 1: conv_body(x1, y1, n); break;
        case 2: conv_body(x2, y2, n); break;
        default: conv_body(x3, y3, n); break;
    }
}

// ---------------------------------------------------------------------------
// Pipelined GEMM: C = (Ah+Al) @ W1 + bias (2 MMA terms).
// Tiles BM=128 BN=64 BK=32; 2-stage ring; 3 CTAs/SM via launch_bounds.
// ---------------------------------------------------------------------------
#define SA 40
#define SB 72
#define APL (128 * SA)           // 5120 el / A plane
#define WPL (32 * SB)            // 2304 el
#define STG (2 * APL + WPL)      // 12544 el / stage
#define STGB (STG * 2)           // 25088 B
#define GSMEM (2 * STGB)         // 50176 B

struct GemmCtx {
    const hf *asrc[4];
    uint adst[4];
    const hf *wsrc;
    uint wdst;
    int wadv;
    uint a_stat, b_stat;
};

__device__ __forceinline__ void gemm_prefetch(const GemmCtx& cx, int it)
{
    const uint so = (uint)((it & 1) * STGB);
    const int ka = it * 32;
#pragma unroll
    for (int i = 0; i < 4; i++)
        cp_async16(cx.adst[i] + so, cx.asrc[i] + ka);
    cp_async16(cx.wdst + so, cx.wsrc + it * cx.wadv);
}

__device__ __forceinline__ void gemm_setup(GemmCtx& cx, uint sm_u32, int tid, int lane,
    const hf* Ah, const hf* Al, int m0,
    const hf* W1, size_t wbase, int ldw, int noff)
{
#pragma unroll
    for (int i = 0; i < 4; i++) {
        int c = i * 256 + tid;
        int quad = c & 3, row = (c >> 2) & 127, plane = (c >> 9) & 1;
        cx.asrc[i] = (plane ? Al : Ah) + (size_t)(m0 + row) * EMB + quad * 8;
        cx.adst[i] = sm_u32 + (uint)((plane * APL + row * SA + quad * 8) * 2);
    }
    {
        int chunk = tid & 7, krow = tid >> 3;    // 32 k-rows x 8 chunks
        cx.wsrc = W1 + (wbase + krow) * (size_t)ldw + noff + chunk * 8;
        cx.wdst = sm_u32 + (uint)((2 * APL + krow * SB + chunk * 8) * 2);
    }
    cx.wadv = 32 * ldw;
    const uint rowpart = (uint)((lane & 7) + 8 * ((lane >> 3) & 1));
    cx.a_stat = sm_u32 + rowpart * (SA * 2) + (uint)((lane >> 4) * 16);
    cx.b_stat = sm_u32 + (uint)(2 * APL * 2) + rowpart * (SB * 2)
              + (uint)((lane >> 4) * 16);
    gemm_prefetch(cx, 0);
    CP_COMMIT();
    gemm_prefetch(cx, 1);
    CP_COMMIT();
}

__device__ __forceinline__ void gemm_mainloop(GemmCtx& cx, float acc[2][4][4],
                                              int wm, int wn)
{
#pragma unroll 1
    for (int it = 0; it < 32; it++) {
        CP_WAIT1();              // tile it resident
        __syncthreads();

        const uint so = (uint)((it & 1) * STGB);
#pragma unroll
        for (int ks = 0; ks < 2; ks++) {
            uint ah[2][4], al[2][4];
#pragma unroll
            for (int i = 0; i < 2; i++) {
                const uint ab = cx.a_stat + so
                              + (uint)((wm * 32 + 16 * i) * SA * 2 + ks * 32);
                LDSM4(ah[i][0], ah[i][1], ah[i][2], ah[i][3], ab);
                LDSM4(al[i][0], al[i][1], al[i][2], al[i][3], ab + APL * 2);
            }
#pragma unroll
            for (int jp = 0; jp < 2; jp++) {
                uint r0, r1, r2, r3;
                LDSM4T(r0, r1, r2, r3,
                       cx.b_stat + so + (uint)(ks * 16 * SB * 2 + (wn * 32 + jp * 16) * 2));
#pragma unroll
                for (int i = 0; i < 2; i++) {
                    MMA_F16(acc[i][2 * jp],     ah[i][0], ah[i][1], ah[i][2], ah[i][3], r0, r1);
                    MMA_F16(acc[i][2 * jp],     al[i][0], al[i][1], al[i][2], al[i][3], r0, r1);
                    MMA_F16(acc[i][2 * jp + 1], ah[i][0], ah[i][1], ah[i][2], ah[i][3], r2, r3);
                    MMA_F16(acc[i][2 * jp + 1], al[i][0], al[i][1], al[i][2], al[i][3], r2, r3);
                }
            }
        }
        __syncthreads();         // all reads of buffer (it&1) done

        if (it + 2 < 32) gemm_prefetch(cx, it + 2);   // safe: buffer free now
        CP_COMMIT();
    }
}

// ---- fused QKV: grid (16 heads, 32 m-blocks, 3) ----
__global__ void __launch_bounds__(256, 3) qkv_gemm(
    const hf* __restrict__ dech, const hf* __restrict__ decl,
    const hf* __restrict__ ench, const hf* __restrict__ encl,
    const hf* __restrict__ wq1, const hf* __restrict__ wk1,
    const hf* __restrict__ wv1,
    const float* __restrict__ bq, const float* __restrict__ bk,
    const float* __restrict__ bv,
    hf* __restrict__ Qf, hf* __restrict__ Kf, hf* __restrict__ Vtf)
{
    extern __shared__ hf smg[];
    const int z = blockIdx.z;
    const int head = blockIdx.x;
    const int m0 = blockIdx.y * 128;
    const int tid = threadIdx.x;
    const int lane = tid & 31, wid = tid >> 5;
    const int wm = wid & 3, wn = wid >> 2;
    const int g = lane >> 2, tig = lane & 3;

    const hf *Ah, *Al, *W1; const float* bias;
    if (z == 0)      { Ah = dech; Al = decl; W1 = wq1; bias = bq; }
    else if (z == 1) { Ah = ench; Al = encl; W1 = wk1; bias = bk; }
    else             { Ah = ench; Al = encl; W1 = wv1; bias = bv; }

    GemmCtx cx;
    gemm_setup(cx, (uint)__cvta_generic_to_shared(smg), tid, lane,
               Ah, Al, m0, W1, (size_t)head * EMB, DH, 0);

    float acc[2][4][4] = {};
    gemm_mainloop(cx, acc, wm, wn);

#pragma unroll
    for (int i = 0; i < 2; i++) {
        const int r0 = m0 + wm * 32 + 16 * i + g;
        const int r1 = r0 + 8;
#pragma unroll
        for (int j = 0; j < 4; j++) {
            const int d = wn * 32 + 8 * j + 2 * tig;
            float v00 = acc[i][j][0] + bias[head * DH + d];
            float v01 = acc[i][j][1] + bias[head * DH + d + 1];
            float v10 = acc[i][j][2] + bias[head * DH + d];
            float v11 = acc[i][j][3] + bias[head * DH + d + 1];
            if (z == 0) { v00 *= QSCALE; v01 *= QSCALE; v10 *= QSCALE; v11 *= QSCALE; }

            const int b0_ = r0 >> 11, q0_ = r0 & 2047;
            const int b1_ = r1 >> 11, q1_ = r1 & 2047;
            if (z < 2) {
                hf* O = z ? Kf : Qf;
                size_t i0 = (((size_t)b0_ * NH + head) * SEQ + q0_) * DH + d;
                *(uint*)(O + i0) = pack_h2(v00, v01);
                size_t i1 = (((size_t)b1_ * NH + head) * SEQ + q1_) * DH + d;
                *(uint*)(O + i1) = pack_h2(v10, v11);
            } else {
                size_t base0 = (((size_t)b0_ * NH + head) * DH + d) * SEQ;
                size_t base1 = (((size_t)b1_ * NH + head) * DH + d) * SEQ;
                Vtf[base0 + q0_]       = __float2half_rn(v00);
                Vtf[base0 + SEQ + q0_] = __float2half_rn(v01);
                Vtf[base1 + q1_]       = __float2half_rn(v10);
                Vtf[base1 + SEQ + q1_] = __float2half_rn(v11);
            }
        }
    }
}

// ---- output projection: grid (16 n-blocks, 32 m-blocks) ----
__global__ void __launch_bounds__(256, 3) wo_gemm(
    const hf* __restrict__ Ah, const hf* __restrict__ Al,
    const hf* __restrict__ W1,
    const float* __restrict__ bias, float* __restrict__ Of)
{
    extern __shared__ hf smg[];
    const int n0 = blockIdx.x * 64;
    const int m0 = blockIdx.y * 128;
    const int tid = threadIdx.x;
    const int lane = tid & 31, wid = tid >> 5;
    const int wm = wid & 3, wn = wid >> 2;
    const int g = lane >> 2, tig = lane & 3;

    GemmCtx cx;
    gemm_setup(cx, (uint)__cvta_generic_to_shared(smg), tid, lane,
               Ah, Al, m0, W1, 0, EMB, n0);

    float acc[2][4][4] = {};
    gemm_mainloop(cx, acc, wm, wn);

#pragma unroll
    for (int i = 0; i < 2; i++) {
        const int r0 = m0 + wm * 32 + 16 * i + g;
        const int r1 = r0 + 8;
#pragma unroll
        for (int j = 0; j < 4; j++) {
            const int c = n0 + wn * 32 + 8 * j + 2 * tig;
            Of[(size_t)r0 * EMB + c]     = acc[i][j][0] + bias[c];
            Of[(size_t)r0 * EMB + c + 1] = acc[i][j][1] + bias[c + 1];
            Of[(size_t)r1 * EMB + c]     = acc[i][j][2] + bias[c];
            Of[(size_t)r1 * EMB + c + 1] = acc[i][j][3] + bias[c + 1];
        }
    }
}

// ---------------------------------------------------------------------------
// Flash attention, single fp16. 3-stage K/V ring, ONE barrier per tile
// (prefetch of t+2 issued right after the barrier, overlapping compute).
// ex2.approx.f16x2 softmax. Block = 128 q rows, 8 warps x 16 rows.
// ---------------------------------------------------------------------------
#define ST 72
#define QPLB (128 * ST * 2)      // 18432 B Q plane
#define KVPLB (64 * ST * 2)      // 9216 B per K/V plane
#define STAGEB (2 * KVPLB)       // 18432 B per stage
#define ASMEM (QPLB + 3 * STAGEB)  // 73728 B

__global__ void __launch_bounds__(256, 3) attn_mma(
    const hf* __restrict__ Qf, const hf* __restrict__ Kf,
    const hf* __restrict__ Vtf,
    hf* __restrict__ Ch, hf* __restrict__ Cl)
{
    extern __shared__ hf sm[];

    const int bh = blockIdx.y;
    const int q0 = blockIdx.x * 128;
    const int tid = threadIdx.x;
    const int lane = tid & 31, wid = tid >> 5;
    const int g = lane >> 2, tig = lane & 3;

    const size_t qkbase = (size_t)bh * SEQ * DH;
    const uint smb = (uint)__cvta_generic_to_shared(sm);

    const uint a_off = (uint)(((lane & 7) + 8 * ((lane >> 3) & 1)) * (ST * 2))
                     + (uint)((lane >> 4) * 16);
    const uint b_off = (uint)(((lane & 7) + 8 * (lane >> 4)) * (ST * 2))
                     + (uint)(((lane >> 3) & 1) * 16);
    const uint q_stat = smb + a_off + (uint)(wid * 16 * ST * 2);
    const uint k_stat = smb + QPLB + b_off;
    const uint v_stat = k_stat + KVPLB;

    // ---- cp.async sources (per thread: 2 K + 2 V chunks per tile) ----
    const int krow = tid >> 3, kch = tid & 7;
    const hf* kp = Kf + qkbase + (size_t)krow * DH + kch * 8;
    const hf* vp = Vtf + ((size_t)bh * DH + krow) * SEQ + kch * 8;
    const uint kd = smb + QPLB + (uint)((krow * ST + kch * 8) * 2);
    const uint vd = kd + KVPLB;

    // ---- prologue: Q plane + tiles 0,1 ----
    {
        const hf* qs = Qf + qkbase + (size_t)(q0 + (tid >> 1)) * DH + (tid & 1) * 32;
        const uint qd = smb + (uint)(((tid >> 1) * ST + (tid & 1) * 32) * 2);
#pragma unroll
        for (int c = 0; c < 4; c++) cp_async16(qd + c * 16, qs + c * 8);
    }
    cp_async16(kd, kp);                       cp_async16(kd + 32 * ST * 2, kp + 32 * DH);
    cp_async16(vd, vp);                       cp_async16(vd + 32 * ST * 2, vp + 32 * SEQ);
    CP_COMMIT();
    cp_async16(kd + STAGEB, kp + 64 * DH);    cp_async16(kd + STAGEB + 32 * ST * 2, kp + 96 * DH);
    cp_async16(vd + STAGEB, vp + 64);         cp_async16(vd + STAGEB + 32 * ST * 2, vp + 64 + 32 * SEQ);
    CP_COMMIT();

    float l0 = 0.f, l1 = 0.f;
    float o[8][4] = {};

#pragma unroll 1
    for (int t = 0; t < 32; t++) {
        const uint so = (uint)((t % 3) * STAGEB);

        CP_WAIT1();              // tile t resident (newest pending = t+1)
        __syncthreads();         // also: everyone done reading stage (t+2)%3

        // ---- prefetch tile t+2 (overlaps the whole compute below) ----
        if (t + 2 < 32) {
            const uint sd = (uint)(((t + 2) % 3) * STAGEB);
            const hf* ks = kp + (size_t)(t + 2) * 64 * DH;
            const hf* vs = vp + (t + 2) * 64;
            cp_async16(kd + sd, ks);
            cp_async16(kd + sd + 32 * ST * 2, ks + 32 * DH);
            cp_async16(vd + sd, vs);
            cp_async16(vd + sd + 32 * ST * 2, vs + 32 * SEQ);
        }
        CP_COMMIT();

        // ---- S = Q K^T ----
        float s[8][4] = {};
#pragma unroll
        for (int kk = 0; kk < 4; kk++) {
            uint qa0, qa1, qa2, qa3;
            LDSM4(qa0, qa1, qa2, qa3, q_stat + (uint)(kk * 32));
#pragma unroll
            for (int jp = 0; jp < 4; jp++) {
                uint r0, r1, r2, r3;
                LDSM4(r0, r1, r2, r3, k_stat + so + (uint)(jp * 16 * ST * 2 + kk * 32));
                MMA_F16(s[2 * jp],     qa0, qa1, qa2, qa3, r0, r1);
                MMA_F16(s[2 * jp + 1], qa0, qa1, qa2, qa3, r2, r3);
            }
        }

        // ---- softmax: pack to half2 FIRST, exp2 in f16x2 (half the MUFU) ----
#pragma unroll
        for (int kk = 0; kk < 4; kk++) {
            const int j0 = 2 * kk, j1 = 2 * kk + 1;
            const uint pa0 = ex2_h2(pack_h2(s[j0][0], s[j0][1]));
            const uint pa1 = ex2_h2(pack_h2(s[j0][2], s[j0][3]));
            const uint pa2 = ex2_h2(pack_h2(s[j1][0], s[j1][1]));
            const uint pa3 = ex2_h2(pack_h2(s[j1][2], s[j1][3]));
            {
                __half2 t0 = __hadd2(*(const __half2*)&pa0, *(const __half2*)&pa2);
                __half2 t1 = __hadd2(*(const __half2*)&pa1, *(const __half2*)&pa3);
                l0 += __low2float(t0) + __high2float(t0);
                l1 += __low2float(t1) + __high2float(t1);
            }
#pragma unroll
            for (int jp = 0; jp < 4; jp++) {
                uint r0, r1, r2, r3;
                LDSM4(r0, r1, r2, r3, v_stat + so + (uint)(jp * 16 * ST * 2 + kk * 32));
                MMA_F16(o[2 * jp],     pa0, pa1, pa2, pa3, r0, r1);
                MMA_F16(o[2 * jp + 1], pa0, pa1, pa2, pa3, r2, r3);
            }
        }
        // no trailing barrier: next iteration's barrier protects stage reuse
    }

    l0 += __shfl_xor_sync(0xffffffffu, l0, 1);
    l0 += __shfl_xor_sync(0xffffffffu, l0, 2);
    l1 += __shfl_xor_sync(0xffffffffu, l1, 1);
    l1 += __shfl_xor_sync(0xffffffffu, l1, 2);
    const float inv0 = 1.0f / l0, inv1 = 1.0f / l1;

    const int b = bh >> 4, h = bh & 15;
    const int row0 = q0 + wid * 16 + g;
    const size_t m0g = (size_t)b * SEQ + row0;
    const size_t m1g = m0g + 8;
#pragma unroll
    for (int j = 0; j < 8; j++) {
        const int col = h * 64 + 8 * j + 2 * tig;
        uint hh, ll;
        split_pair_h(o[j][0] * inv0, o[j][1] * inv0, hh, ll);
        *(uint*)(Ch + m0g * EMB + col) = hh;
        *(uint*)(Cl + m0g * EMB + col) = ll;
        split_pair_h(o[j][2] * inv1, o[j][3] * inv1, hh, ll);
        *(uint*)(Ch + m1g * EMB + col) = hh;
        *(uint*)(Cl + m1g * EMB + col) = ll;
    }
}

// ---------------------------------------------------------------------------
extern "C" void kernel_launch(void* const* d_in, const int* in_sizes, int n_in,
                              void* d_out, int out_size)
{
    const float* dec = (const float*)d_in[0];
    const float* enc = (const float*)d_in[1];
    const float* wq  = (const float*)d_in[2];
    const float* bq  = (const float*)d_in[3];
    const float* wk  = (const float*)d_in[4];
    const float* bk  = (const float*)d_in[5];
    const float* wv  = (const float*)d_in[6];
    const float* bv  = (const float*)d_in[7];
    const float* wo  = (const float*)d_in[8];
    const float* bo  = (const float*)d_in[9];
    float* out = (float*)d_out;

    hf *dech, *decl, *ench, *encl;
    hf *wq1, *wk1, *wv1, *wo1;
    hf *qf, *kf, *vtf, *ctxh, *ctxl;
    cudaGetSymbolAddress((void**)&dech, g_dech); cudaGetSymbolAddress((void**)&decl, g_decl);
    cudaGetSymbolAddress((void**)&ench, g_ench); cudaGetSymbolAddress((void**)&encl, g_encl);
    cudaGetSymbolAddress((void**)&wq1, g_wq1);   cudaGetSymbolAddress((void**)&wk1, g_wk1);
    cudaGetSymbolAddress((void**)&wv1, g_wv1);   cudaGetSymbolAddress((void**)&wo1, g_wo1);
    cudaGetSymbolAddress((void**)&qf, g_Qf);     cudaGetSymbolAddress((void**)&kf, g_Kf);
    cudaGetSymbolAddress((void**)&vtf, g_Vtf);
    cudaGetSymbolAddress((void**)&ctxh, g_ctxh); cudaGetSymbolAddress((void**)&ctxl, g_ctxl);

    cudaFuncSetAttribute(attn_mma, cudaFuncAttributeMaxDynamicSharedMemorySize, ASMEM);
    cudaFuncSetAttribute(qkv_gemm, cudaFuncAttributeMaxDynamicSharedMemorySize, GSMEM);
    cudaFuncSetAttribute(wo_gemm,  cudaFuncAttributeMaxDynamicSharedMemorySize, GSMEM);

    // 1) activations split-2 fp16; weights single fp16
    const int nAct = MTOT * EMB;
    const int nW   = EMB * EMB;
    dim3 gduo(nAct / 512, 2);
    split_duo<<<gduo, 256>>>(dec, dech, decl, enc, ench, encl, nAct);
    dim3 gquad(nW / 512, 4);
    conv_quad<<<gquad, 256>>>(wq, wq1, wk, wk1, wv, wv1, wo, wo1, nW);

    // 2) fused QKV projections
    dim3 gqkv(NH, MTOT / 128, 3);
    qkv_gemm<<<gqkv, 256, GSMEM>>>(dech, decl, ench, encl,
                                   wq1, wk1, wv1, bq, bk, bv,
                                   qf, kf, vtf);

    // 3) attention
    dim3 gattn(SEQ / 128, BB * NH);
    attn_mma<<<gattn, 256, ASMEM>>>(qf, kf, vtf, ctxh, ctxl);

    // 4) output projection (fp32 out)
    dim3 gwo(EMB / 64, MTOT / 128);
    wo_gemm<<<gwo, 256, GSMEM>>>(ctxh, ctxl, wo1, bo, out);
}

// round 12
// speedup vs baseline: 2.8351x; 1.3713x over previous
#include <cuda_runtime.h>
#include <cuda_fp16.h>
#include <math.h>

typedef unsigned int uint;
typedef __half hf;

#define BB 2
#define SEQ 2048
#define EMB 1024
#define NH 16
#define DH 64
#define MTOT (BB * SEQ)          // 4096

// 0.125 * log2(e)
#define QSCALE 0.18033688011112042f

// ---------------- fp16 scratch (all single-plane) ----------------
__device__ hf g_dec1[MTOT * EMB];
__device__ hf g_enc1[MTOT * EMB];
__device__ hf g_wq1[NH * EMB * DH];
__device__ hf g_wk1[NH * EMB * DH];
__device__ hf g_wv1[NH * EMB * DH];
__device__ hf g_wo1[EMB * EMB];
__device__ hf g_Qf[BB * NH * SEQ * DH];
__device__ hf g_Kf[BB * NH * SEQ * DH];
__device__ hf g_Vtf[BB * NH * DH * SEQ];                // [bh][d][key]
__device__ hf g_ctx1[MTOT * EMB];

// ---------------- helpers ----------------
__device__ __forceinline__ uint pack_h2(float lo, float hi) {
    __half2 v = __floats2half2_rn(lo, hi);
    return *(uint*)&v;
}
__device__ __forceinline__ float fast_ex2(float x) {
    float y; asm("ex2.approx.f32 %0, %1;" : "=f"(y) : "f"(x)); return y;
}

#define MMA_F16(d, a0, a1, a2, a3, b0, b1)                                     \
    asm volatile(                                                              \
        "mma.sync.aligned.m16n8k16.row.col.f32.f16.f16.f32 "                   \
        "{%0,%1,%2,%3}, {%4,%5,%6,%7}, {%8,%9}, {%0,%1,%2,%3};"                \
        : "+f"(d[0]), "+f"(d[1]), "+f"(d[2]), "+f"(d[3])                       \
        : "r"(a0), "r"(a1), "r"(a2), "r"(a3), "r"(b0), "r"(b1))

#define LDSM4(r0, r1, r2, r3, addr)                                            \
    asm volatile("ldmatrix.sync.aligned.m8n8.x4.shared.b16 {%0,%1,%2,%3}, [%4];" \
        : "=r"(r0), "=r"(r1), "=r"(r2), "=r"(r3) : "r"(addr))

#define LDSM4T(r0, r1, r2, r3, addr)                                           \
    asm volatile("ldmatrix.sync.aligned.m8n8.x4.trans.shared.b16 {%0,%1,%2,%3}, [%4];" \
        : "=r"(r0), "=r"(r1), "=r"(r2), "=r"(r3) : "r"(addr))

__device__ __forceinline__ void cp_async16(uint saddr, const void* gptr) {
    asm volatile("cp.async.cg.shared.global [%0], [%1], 16;" :: "r"(saddr), "l"(gptr));
}
#define CP_COMMIT() asm volatile("cp.async.commit_group;")
#define CP_WAIT1()  asm volatile("cp.async.wait_group 1;")

// ---------------- convert kernels: fp32 -> fp16 ----------------
__device__ __forceinline__ void conv_body(const float* __restrict__ x,
    hf* __restrict__ y, int n)
{
    int i = (blockIdx.x * 256 + threadIdx.x) * 2;
    if (i < n) {
        float2 v = *(const float2*)(x + i);
        *(uint*)(y + i) = pack_h2(v.x, v.y);
    }
}

__global__ void __launch_bounds__(256) conv_duo(
    const float* __restrict__ x0, hf* y0,
    const float* __restrict__ x1, hf* y1, int n)
{
    if (blockIdx.y == 0) conv_body(x0, y0, n);
    else                 conv_body(x1, y1, n);
}

__global__ void __launch_bounds__(256) conv_quad(
    const float* __restrict__ x0, hf* y0, const float* __restrict__ x1, hf* y1,
    const float* __restrict__ x2, hf* y2, const float* __restrict__ x3, hf* y3, int n)
{
    switch (blockIdx.y) {
        case 0: conv_body(x0, y0, n); break;
        case 1: conv_body(x1, y1, n); break;
        case 2: conv_body(x2, y2, n); break;
        default: conv_body(x3, y3, n); break;
    }
}

// ---------------------------------------------------------------------------
// Pipelined GEMM, single fp16 x single fp16 (1 MMA term).
// Tiles BM=128 BN=64 BK=32; A [m][k] stride SA; W [k][n] stride SB (LDSM4T).
// 2-stage cp.async ring; prefetch after consume barrier.
// 8 warps (4m x 2n), per-warp 32m x 32n.
// ---------------------------------------------------------------------------
#define SA 40
#define SB 72
#define APL (128 * SA)           // 5120 el A plane
#define WPL (32 * SB)            // 2304 el
#define STG (APL + WPL)          // 7424 el / stage
#define STGB (STG * 2)           // 14848 B
#define GSMEM (2 * STGB)         // 29696 B

struct GemmCtx {
    const hf *asrc[2];
    uint adst[2];
    const hf *wsrc;
    uint wdst;
    int wadv;
    uint a_stat, b_stat;
};

__device__ __forceinline__ void gemm_prefetch(const GemmCtx& cx, int it)
{
    const uint so = (uint)((it & 1) * STGB);
    const int ka = it * 32;
#pragma unroll
    for (int i = 0; i < 2; i++)
        cp_async16(cx.adst[i] + so, cx.asrc[i] + ka);
    cp_async16(cx.wdst + so, cx.wsrc + it * cx.wadv);
}

__device__ __forceinline__ void gemm_setup(GemmCtx& cx, uint sm_u32, int tid, int lane,
    const hf* A1, int m0,
    const hf* W1, size_t wbase, int ldw, int noff)
{
#pragma unroll
    for (int i = 0; i < 2; i++) {
        int c = i * 256 + tid;
        int quad = c & 3, row = (c >> 2) & 127;
        cx.asrc[i] = A1 + (size_t)(m0 + row) * EMB + quad * 8;
        cx.adst[i] = sm_u32 + (uint)((row * SA + quad * 8) * 2);
    }
    {
        int chunk = tid & 7, krow = tid >> 3;    // 32 k-rows x 8 chunks
        cx.wsrc = W1 + (wbase + krow) * (size_t)ldw + noff + chunk * 8;
        cx.wdst = sm_u32 + (uint)((APL + krow * SB + chunk * 8) * 2);
    }
    cx.wadv = 32 * ldw;
    const uint rowpart = (uint)((lane & 7) + 8 * ((lane >> 3) & 1));
    cx.a_stat = sm_u32 + rowpart * (SA * 2) + (uint)((lane >> 4) * 16);
    cx.b_stat = sm_u32 + (uint)(APL * 2) + rowpart * (SB * 2)
              + (uint)((lane >> 4) * 16);
    gemm_prefetch(cx, 0);
    CP_COMMIT();
    gemm_prefetch(cx, 1);
    CP_COMMIT();
}

__device__ __forceinline__ void gemm_mainloop(GemmCtx& cx, float acc[2][4][4],
                                              int wm, int wn)
{
#pragma unroll 1
    for (int it = 0; it < 32; it++) {
        CP_WAIT1();              // tile it resident
        __syncthreads();

        const uint so = (uint)((it & 1) * STGB);
#pragma unroll
        for (int ks = 0; ks < 2; ks++) {
            uint ah[2][4];
#pragma unroll
            for (int i = 0; i < 2; i++) {
                const uint ab = cx.a_stat + so
                              + (uint)((wm * 32 + 16 * i) * SA * 2 + ks * 32);
                LDSM4(ah[i][0], ah[i][1], ah[i][2], ah[i][3], ab);
            }
#pragma unroll
            for (int jp = 0; jp < 2; jp++) {
                uint r0, r1, r2, r3;
                LDSM4T(r0, r1, r2, r3,
                       cx.b_stat + so + (uint)(ks * 16 * SB * 2 + (wn * 32 + jp * 16) * 2));
#pragma unroll
                for (int i = 0; i < 2; i++) {
                    MMA_F16(acc[i][2 * jp],     ah[i][0], ah[i][1], ah[i][2], ah[i][3], r0, r1);
                    MMA_F16(acc[i][2 * jp + 1], ah[i][0], ah[i][1], ah[i][2], ah[i][3], r2, r3);
                }
            }
        }
        __syncthreads();         // all reads of buffer (it&1) done

        if (it + 2 < 32) gemm_prefetch(cx, it + 2);   // buffer free now
        CP_COMMIT();
    }
}

// ---- fused QKV: grid (16 heads, 32 m-blocks, 3) ----
__global__ void __launch_bounds__(256, 3) qkv_gemm(
    const hf* __restrict__ dec1, const hf* __restrict__ enc1,
    const hf* __restrict__ wq1, const hf* __restrict__ wk1,
    const hf* __restrict__ wv1,
    const float* __restrict__ bq, const float* __restrict__ bk,
    const float* __restrict__ bv,
    hf* __restrict__ Qf, hf* __restrict__ Kf, hf* __restrict__ Vtf)
{
    extern __shared__ hf smg[];
    const int z = blockIdx.z;
    const int head = blockIdx.x;
    const int m0 = blockIdx.y * 128;
    const int tid = threadIdx.x;
    const int lane = tid & 31, wid = tid >> 5;
    const int wm = wid & 3, wn = wid >> 2;
    const int g = lane >> 2, tig = lane & 3;

    const hf *A1, *W1; const float* bias;
    if (z == 0)      { A1 = dec1; W1 = wq1; bias = bq; }
    else if (z == 1) { A1 = enc1; W1 = wk1; bias = bk; }
    else             { A1 = enc1; W1 = wv1; bias = bv; }

    GemmCtx cx;
    gemm_setup(cx, (uint)__cvta_generic_to_shared(smg), tid, lane,
               A1, m0, W1, (size_t)head * EMB, DH, 0);

    float acc[2][4][4] = {};
    gemm_mainloop(cx, acc, wm, wn);

#pragma unroll
    for (int i = 0; i < 2; i++) {
        const int r0 = m0 + wm * 32 + 16 * i + g;
        const int r1 = r0 + 8;
#pragma unroll
        for (int j = 0; j < 4; j++) {
            const int d = wn * 32 + 8 * j + 2 * tig;
            float v00 = acc[i][j][0] + bias[head * DH + d];
            float v01 = acc[i][j][1] + bias[head * DH + d + 1];
            float v10 = acc[i][j][2] + bias[head * DH + d];
            float v11 = acc[i][j][3] + bias[head * DH + d + 1];
            if (z == 0) { v00 *= QSCALE; v01 *= QSCALE; v10 *= QSCALE; v11 *= QSCALE; }

            const int b0_ = r0 >> 11, q0_ = r0 & 2047;
            const int b1_ = r1 >> 11, q1_ = r1 & 2047;
            if (z < 2) {
                hf* O = z ? Kf : Qf;
                size_t i0 = (((size_t)b0_ * NH + head) * SEQ + q0_) * DH + d;
                *(uint*)(O + i0) = pack_h2(v00, v01);
                size_t i1 = (((size_t)b1_ * NH + head) * SEQ + q1_) * DH + d;
                *(uint*)(O + i1) = pack_h2(v10, v11);
            } else {
                size_t base0 = (((size_t)b0_ * NH + head) * DH + d) * SEQ;
                size_t base1 = (((size_t)b1_ * NH + head) * DH + d) * SEQ;
                Vtf[base0 + q0_]       = __float2half_rn(v00);
                Vtf[base0 + SEQ + q0_] = __float2half_rn(v01);
                Vtf[base1 + q1_]       = __float2half_rn(v10);
                Vtf[base1 + SEQ + q1_] = __float2half_rn(v11);
            }
        }
    }
}

// ---- output projection: grid (16 n-blocks, 32 m-blocks) ----
__global__ void __launch_bounds__(256, 3) wo_gemm(
    const hf* __restrict__ A1, const hf* __restrict__ W1,
    const float* __restrict__ bias, float* __restrict__ Of)
{
    extern __shared__ hf smg[];
    const int n0 = blockIdx.x * 64;
    const int m0 = blockIdx.y * 128;
    const int tid = threadIdx.x;
    const int lane = tid & 31, wid = tid >> 5;
    const int wm = wid & 3, wn = wid >> 2;
    const int g = lane >> 2, tig = lane & 3;

    GemmCtx cx;
    gemm_setup(cx, (uint)__cvta_generic_to_shared(smg), tid, lane,
               A1, m0, W1, 0, EMB, n0);

    float acc[2][4][4] = {};
    gemm_mainloop(cx, acc, wm, wn);

#pragma unroll
    for (int i = 0; i < 2; i++) {
        const int r0 = m0 + wm * 32 + 16 * i + g;
        const int r1 = r0 + 8;
#pragma unroll
        for (int j = 0; j < 4; j++) {
            const int c = n0 + wn * 32 + 8 * j + 2 * tig;
            Of[(size_t)r0 * EMB + c]     = acc[i][j][0] + bias[c];
            Of[(size_t)r0 * EMB + c + 1] = acc[i][j][1] + bias[c + 1];
            Of[(size_t)r1 * EMB + c]     = acc[i][j][2] + bias[c];
            Of[(size_t)r1 * EMB + c + 1] = acc[i][j][3] + bias[c + 1];
        }
    }
}

// ---------------------------------------------------------------------------
// Flash attention (round-10 version, single fp16): Q in smem, K/V 2-stage
// cp.async ring, fp32 ex2 softmax, single-plane ctx output.
// Block = 128 q rows of one (b,h), 8 warps x 16 rows.
// ---------------------------------------------------------------------------
#define ST 72
#define QPLB (128 * ST * 2)      // 18432 B Q plane
#define KVPLB (64 * ST * 2)      // 9216 B per K/V plane
#define STAGEB (2 * KVPLB)       // 18432 B per stage
#define ASMEM (QPLB + 2 * STAGEB)  // 55296 B

__global__ void __launch_bounds__(256, 3) attn_mma(
    const hf* __restrict__ Qf, const hf* __restrict__ Kf,
    const hf* __restrict__ Vtf,
    hf* __restrict__ Cf)
{
    extern __shared__ hf sm[];

    const int bh = blockIdx.y;
    const int q0 = blockIdx.x * 128;
    const int tid = threadIdx.x;
    const int lane = tid & 31, wid = tid >> 5;
    const int g = lane >> 2, tig = lane & 3;

    const size_t qkbase = (size_t)bh * SEQ * DH;
    const uint smb = (uint)__cvta_generic_to_shared(sm);

    const uint a_off = (uint)(((lane & 7) + 8 * ((lane >> 3) & 1)) * (ST * 2))
                     + (uint)((lane >> 4) * 16);
    const uint b_off = (uint)(((lane & 7) + 8 * (lane >> 4)) * (ST * 2))
                     + (uint)(((lane >> 3) & 1) * 16);
    const uint q_stat = smb + a_off + (uint)(wid * 16 * ST * 2);
    const uint k_stat = smb + QPLB + b_off;
    const uint v_stat = k_stat + KVPLB;

    // ---- cp.async sources ----
    const int krow = tid >> 3, kch = tid & 7;
    const hf* kp = Kf + qkbase + (size_t)krow * DH + kch * 8;
    const hf* vp = Vtf + ((size_t)bh * DH + krow) * SEQ + kch * 8;
    const uint kd = smb + QPLB + (uint)((krow * ST + kch * 8) * 2);
    const uint vd = kd + KVPLB;

    // ---- prologue: Q plane + tiles 0,1 ----
    {
        const hf* qs = Qf + qkbase + (size_t)(q0 + (tid >> 1)) * DH + (tid & 1) * 32;
        const uint qd = smb + (uint)(((tid >> 1) * ST + (tid & 1) * 32) * 2);
#pragma unroll
        for (int c = 0; c < 4; c++) cp_async16(qd + c * 16, qs + c * 8);
    }
    cp_async16(kd, kp);                       cp_async16(kd + 32 * ST * 2, kp + 32 * DH);
    cp_async16(vd, vp);                       cp_async16(vd + 32 * ST * 2, vp + 32 * SEQ);
    CP_COMMIT();
    cp_async16(kd + STAGEB, kp + 64 * DH);    cp_async16(kd + STAGEB + 32 * ST * 2, kp + 96 * DH);
    cp_async16(vd + STAGEB, vp + 64);         cp_async16(vd + STAGEB + 32 * ST * 2, vp + 64 + 32 * SEQ);
    CP_COMMIT();

    float l0 = 0.f, l1 = 0.f;
    float o[8][4] = {};

#pragma unroll 1
    for (int t = 0; t < 32; t++) {
        const uint so = (uint)((t & 1) * STAGEB);

        CP_WAIT1();
        __syncthreads();

        // ---- S = Q K^T ----
        float s[8][4] = {};
#pragma unroll
        for (int kk = 0; kk < 4; kk++) {
            uint qa0, qa1, qa2, qa3;
            LDSM4(qa0, qa1, qa2, qa3, q_stat + (uint)(kk * 32));
#pragma unroll
            for (int jp = 0; jp < 4; jp++) {
                uint r0, r1, r2, r3;
                LDSM4(r0, r1, r2, r3, k_stat + so + (uint)(jp * 16 * ST * 2 + kk * 32));
                MMA_F16(s[2 * jp],     qa0, qa1, qa2, qa3, r0, r1);
                MMA_F16(s[2 * jp + 1], qa0, qa1, qa2, qa3, r2, r3);
            }
        }

        // ---- softmax (fp32 ex2, no max-sub) + P@V ----
#pragma unroll
        for (int kk = 0; kk < 4; kk++) {
            const int j0 = 2 * kk, j1 = 2 * kk + 1;
            float p00 = fast_ex2(s[j0][0]), p01 = fast_ex2(s[j0][1]);
            float p02 = fast_ex2(s[j0][2]), p03 = fast_ex2(s[j0][3]);
            float p10 = fast_ex2(s[j1][0]), p11 = fast_ex2(s[j1][1]);
            float p12 = fast_ex2(s[j1][2]), p13 = fast_ex2(s[j1][3]);
            l0 += p00 + p01 + p10 + p11;
            l1 += p02 + p03 + p12 + p13;
            const uint pa0 = pack_h2(p00, p01);
            const uint pa1 = pack_h2(p02, p03);
            const uint pa2 = pack_h2(p10, p11);
            const uint pa3 = pack_h2(p12, p13);
#pragma unroll
            for (int jp = 0; jp < 4; jp++) {
                uint r0, r1, r2, r3;
                LDSM4(r0, r1, r2, r3, v_stat + so + (uint)(jp * 16 * ST * 2 + kk * 32));
                MMA_F16(o[2 * jp],     pa0, pa1, pa2, pa3, r0, r1);
                MMA_F16(o[2 * jp + 1], pa0, pa1, pa2, pa3, r2, r3);
            }
        }

        __syncthreads();

        // ---- prefetch tile t+2 into the buffer just freed ----
        if (t + 2 < 32) {
            const uint sd = (uint)((t & 1) * STAGEB);
            const hf* ks = kp + (size_t)(t + 2) * 64 * DH;
            const hf* vs = vp + (t + 2) * 64;
            cp_async16(kd + sd, ks);
            cp_async16(kd + sd + 32 * ST * 2, ks + 32 * DH);
            cp_async16(vd + sd, vs);
            cp_async16(vd + sd + 32 * ST * 2, vs + 32 * SEQ);
        }
        CP_COMMIT();
    }

    l0 += __shfl_xor_sync(0xffffffffu, l0, 1);
    l0 += __shfl_xor_sync(0xffffffffu, l0, 2);
    l1 += __shfl_xor_sync(0xffffffffu, l1, 1);
    l1 += __shfl_xor_sync(0xffffffffu, l1, 2);
    const float inv0 = 1.0f / l0, inv1 = 1.0f / l1;

    const int b = bh >> 4, h = bh & 15;
    const int row0 = q0 + wid * 16 + g;
    const size_t m0g = (size_t)b * SEQ + row0;
    const size_t m1g = m0g + 8;
#pragma unroll
    for (int j = 0; j < 8; j++) {
        const int col = h * 64 + 8 * j + 2 * tig;
        *(uint*)(Cf + m0g * EMB + col) = pack_h2(o[j][0] * inv0, o[j][1] * inv0);
        *(uint*)(Cf + m1g * EMB + col) = pack_h2(o[j][2] * inv1, o[j][3] * inv1);
    }
}

// ---------------------------------------------------------------------------
extern "C" void kernel_launch(void* const* d_in, const int* in_sizes, int n_in,
                              void* d_out, int out_size)
{
    const float* dec = (const float*)d_in[0];
    const float* enc = (const float*)d_in[1];
    const float* wq  = (const float*)d_in[2];
    const float* bq  = (const float*)d_in[3];
    const float* wk  = (const float*)d_in[4];
    const float* bk  = (const float*)d_in[5];
    const float* wv  = (const float*)d_in[6];
    const float* bv  = (const float*)d_in[7];
    const float* wo  = (const float*)d_in[8];
    const float* bo  = (const float*)d_in[9];
    float* out = (float*)d_out;

    hf *dec1, *enc1, *wq1, *wk1, *wv1, *wo1;
    hf *qf, *kf, *vtf, *ctx1;
    cudaGetSymbolAddress((void**)&dec1, g_dec1); cudaGetSymbolAddress((void**)&enc1, g_enc1);
    cudaGetSymbolAddress((void**)&wq1, g_wq1);   cudaGetSymbolAddress((void**)&wk1, g_wk1);
    cudaGetSymbolAddress((void**)&wv1, g_wv1);   cudaGetSymbolAddress((void**)&wo1, g_wo1);
    cudaGetSymbolAddress((void**)&qf, g_Qf);     cudaGetSymbolAddress((void**)&kf, g_Kf);
    cudaGetSymbolAddress((void**)&vtf, g_Vtf);   cudaGetSymbolAddress((void**)&ctx1, g_ctx1);

    cudaFuncSetAttribute(attn_mma, cudaFuncAttributeMaxDynamicSharedMemorySize, ASMEM);
    cudaFuncSetAttribute(qkv_gemm, cudaFuncAttributeMaxDynamicSharedMemorySize, GSMEM);
    cudaFuncSetAttribute(wo_gemm,  cudaFuncAttributeMaxDynamicSharedMemorySize, GSMEM);

    // 1) fp32 -> fp16 converts
    const int nAct = MTOT * EMB;
    const int nW   = EMB * EMB;
    dim3 gduo(nAct / 512, 2);
    conv_duo<<<gduo, 256>>>(dec, dec1, enc, enc1, nAct);
    dim3 gquad(nW / 512, 4);
    conv_quad<<<gquad, 256>>>(wq, wq1, wk, wk1, wv, wv1, wo, wo1, nW);

    // 2) fused QKV projections
    dim3 gqkv(NH, MTOT / 128, 3);
    qkv_gemm<<<gqkv, 256, GSMEM>>>(dec1, enc1, wq1, wk1, wv1,
                                   bq, bk, bv, qf, kf, vtf);

    // 3) attention
    dim3 gattn(SEQ / 128, BB * NH);
    attn_mma<<<gattn, 256, ASMEM>>>(qf, kf, vtf, ctx1);

    // 4) output projection (fp32 out)
    dim3 gwo(EMB / 64, MTOT / 128);
    wo_gemm<<<gwo, 256, GSMEM>>>(ctx1, wo1, bo, out);
}

// round 13
// speedup vs baseline: 2.9648x; 1.0457x over previous
#include <cuda_runtime.h>
#include <cuda_fp16.h>
#include <math.h>

typedef unsigned int uint;
typedef __half hf;

#define BB 2
#define SEQ 2048
#define EMB 1024
#define NH 16
#define DH 64
#define MTOT (BB * SEQ)          // 4096

// 0.125 * log2(e)
#define QSCALE 0.18033688011112042f

// ---------------- fp16 scratch (all single-plane) ----------------
__device__ hf g_dec1[MTOT * EMB];
__device__ hf g_enc1[MTOT * EMB];
__device__ hf g_wq1[NH * EMB * DH];
__device__ hf g_wk1[NH * EMB * DH];
__device__ hf g_wv1[NH * EMB * DH];
__device__ hf g_wo1[EMB * EMB];
__device__ hf g_Qf[BB * NH * SEQ * DH];
__device__ hf g_Kf[BB * NH * SEQ * DH];
__device__ hf g_Vtf[BB * NH * DH * SEQ];                // [bh][d][key]
__device__ hf g_ctx1[MTOT * EMB];

// ---------------- helpers ----------------
__device__ __forceinline__ uint pack_h2(float lo, float hi) {
    __half2 v = __floats2half2_rn(lo, hi);
    return *(uint*)&v;
}
__device__ __forceinline__ float fast_ex2(float x) {
    float y; asm("ex2.approx.f32 %0, %1;" : "=f"(y) : "f"(x)); return y;
}

#define MMA_F16(d, a0, a1, a2, a3, b0, b1)                                     \
    asm volatile(                                                              \
        "mma.sync.aligned.m16n8k16.row.col.f32.f16.f16.f32 "                   \
        "{%0,%1,%2,%3}, {%4,%5,%6,%7}, {%8,%9}, {%0,%1,%2,%3};"                \
        : "+f"(d[0]), "+f"(d[1]), "+f"(d[2]), "+f"(d[3])                       \
        : "r"(a0), "r"(a1), "r"(a2), "r"(a3), "r"(b0), "r"(b1))

#define LDSM4(r0, r1, r2, r3, addr)                                            \
    asm volatile("ldmatrix.sync.aligned.m8n8.x4.shared.b16 {%0,%1,%2,%3}, [%4];" \
        : "=r"(r0), "=r"(r1), "=r"(r2), "=r"(r3) : "r"(addr))

#define LDSM4T(r0, r1, r2, r3, addr)                                           \
    asm volatile("ldmatrix.sync.aligned.m8n8.x4.trans.shared.b16 {%0,%1,%2,%3}, [%4];" \
        : "=r"(r0), "=r"(r1), "=r"(r2), "=r"(r3) : "r"(addr))

__device__ __forceinline__ void cp_async16(uint saddr, const void* gptr) {
    asm volatile("cp.async.cg.shared.global [%0], [%1], 16;" :: "r"(saddr), "l"(gptr));
}
#define CP_COMMIT() asm volatile("cp.async.commit_group;")
#define CP_WAIT1()  asm volatile("cp.async.wait_group 1;")

// ---------------- convert kernels: fp32 -> fp16 ----------------
__device__ __forceinline__ void conv_body(const float* __restrict__ x,
    hf* __restrict__ y, int n)
{
    int i = (blockIdx.x * 256 + threadIdx.x) * 2;
    if (i < n) {
        float2 v = *(const float2*)(x + i);
        *(uint*)(y + i) = pack_h2(v.x, v.y);
    }
}

__global__ void __launch_bounds__(256) conv_duo(
    const float* __restrict__ x0, hf* y0,
    const float* __restrict__ x1, hf* y1, int n)
{
    if (blockIdx.y == 0) conv_body(x0, y0, n);
    else                 conv_body(x1, y1, n);
}

__global__ void __launch_bounds__(256) conv_quad(
    const float* __restrict__ x0, hf* y0, const float* __restrict__ x1, hf* y1,
    const float* __restrict__ x2, hf* y2, const float* __restrict__ x3, hf* y3, int n)
{
    switch (blockIdx.y) {
        case 0: conv_body(x0, y0, n); break;
        case 1: conv_body(x1, y1, n); break;
        case 2: conv_body(x2, y2, n); break;
        default: conv_body(x3, y3, n); break;
    }
}

// ---------------------------------------------------------------------------
// Pipelined GEMM, single fp16 x fp16, BK=64 (32 MMA per warp per barrier).
// Tiles BM=128 BN=64 BK=64; A [m][k] stride SA; W [k][n] stride SB (LDSM4T).
// 2-stage cp.async ring; prefetch after consume barrier. 16 k-iterations.
// 8 warps (4m x 2n), per-warp 32m x 32n.
// ---------------------------------------------------------------------------
#define SA 72
#define SB 72
#define APL (128 * SA)           // 9216 el A plane
#define WPL (64 * SB)            // 4608 el W plane
#define STG (APL + WPL)          // 13824 el / stage
#define STGB (STG * 2)           // 27648 B
#define GSMEM (2 * STGB)         // 55296 B

struct GemmCtx {
    const hf *asrc[4];
    uint adst[4];
    const hf *wsrc[2];
    uint wdst[2];
    int wadv;
    uint a_stat, b_stat;
};

__device__ __forceinline__ void gemm_prefetch(const GemmCtx& cx, int it)
{
    const uint so = (uint)((it & 1) * STGB);
    const int ka = it * 64;
#pragma unroll
    for (int i = 0; i < 4; i++)
        cp_async16(cx.adst[i] + so, cx.asrc[i] + ka);
#pragma unroll
    for (int i = 0; i < 2; i++)
        cp_async16(cx.wdst[i] + so, cx.wsrc[i] + it * cx.wadv);
}

__device__ __forceinline__ void gemm_setup(GemmCtx& cx, uint sm_u32, int tid, int lane,
    const hf* A1, int m0,
    const hf* W1, size_t wbase, int ldw, int noff)
{
    // A: 128 rows x 64 k = 1024 16B-chunks -> 4 per thread
#pragma unroll
    for (int i = 0; i < 4; i++) {
        int c = i * 256 + tid;
        int quad = c & 7, row = (c >> 3) & 127;
        cx.asrc[i] = A1 + (size_t)(m0 + row) * EMB + quad * 8;
        cx.adst[i] = sm_u32 + (uint)((row * SA + quad * 8) * 2);
    }
    // W: 64 k-rows x 64 n = 512 chunks -> 2 per thread
#pragma unroll
    for (int i = 0; i < 2; i++) {
        int c = i * 256 + tid;
        int chunk = c & 7, krow = (c >> 3) & 63;
        cx.wsrc[i] = W1 + (wbase + krow) * (size_t)ldw + noff + chunk * 8;
        cx.wdst[i] = sm_u32 + (uint)((APL + krow * SB + chunk * 8) * 2);
    }
    cx.wadv = 64 * ldw;
    const uint rowpart = (uint)((lane & 7) + 8 * ((lane >> 3) & 1));
    cx.a_stat = sm_u32 + rowpart * (SA * 2) + (uint)((lane >> 4) * 16);
    cx.b_stat = sm_u32 + (uint)(APL * 2) + rowpart * (SB * 2)
              + (uint)((lane >> 4) * 16);
    gemm_prefetch(cx, 0);
    CP_COMMIT();
    gemm_prefetch(cx, 1);
    CP_COMMIT();
}

__device__ __forceinline__ void gemm_mainloop(GemmCtx& cx, float acc[2][4][4],
                                              int wm, int wn)
{
#pragma unroll 1
    for (int it = 0; it < 16; it++) {
        CP_WAIT1();              // tile it resident
        __syncthreads();

        const uint so = (uint)((it & 1) * STGB);
#pragma unroll
        for (int ks = 0; ks < 4; ks++) {
            uint ah[2][4];
#pragma unroll
            for (int i = 0; i < 2; i++) {
                const uint ab = cx.a_stat + so
                              + (uint)((wm * 32 + 16 * i) * SA * 2 + ks * 32);
                LDSM4(ah[i][0], ah[i][1], ah[i][2], ah[i][3], ab);
            }
#pragma unroll
            for (int jp = 0; jp < 2; jp++) {
                uint r0, r1, r2, r3;
                LDSM4T(r0, r1, r2, r3,
                       cx.b_stat + so + (uint)(ks * 16 * SB * 2 + (wn * 32 + jp * 16) * 2));
#pragma unroll
                for (int i = 0; i < 2; i++) {
                    MMA_F16(acc[i][2 * jp],     ah[i][0], ah[i][1], ah[i][2], ah[i][3], r0, r1);
                    MMA_F16(acc[i][2 * jp + 1], ah[i][0], ah[i][1], ah[i][2], ah[i][3], r2, r3);
                }
            }
        }
        __syncthreads();         // all reads of buffer (it&1) done

        if (it + 2 < 16) gemm_prefetch(cx, it + 2);   // buffer free now
        CP_COMMIT();
    }
}

// ---- fused QKV: grid (16 heads, 32 m-blocks, 3) ----
__global__ void __launch_bounds__(256, 3) qkv_gemm(
    const hf* __restrict__ dec1, const hf* __restrict__ enc1,
    const hf* __restrict__ wq1, const hf* __restrict__ wk1,
    const hf* __restrict__ wv1,
    const float* __restrict__ bq, const float* __restrict__ bk,
    const float* __restrict__ bv,
    hf* __restrict__ Qf, hf* __restrict__ Kf, hf* __restrict__ Vtf)
{
    extern __shared__ hf smg[];
    const int z = blockIdx.z;
    const int head = blockIdx.x;
    const int m0 = blockIdx.y * 128;
    const int tid = threadIdx.x;
    const int lane = tid & 31, wid = tid >> 5;
    const int wm = wid & 3, wn = wid >> 2;
    const int g = lane >> 2, tig = lane & 3;

    const hf *A1, *W1; const float* bias;
    if (z == 0)      { A1 = dec1; W1 = wq1; bias = bq; }
    else if (z == 1) { A1 = enc1; W1 = wk1; bias = bk; }
    else             { A1 = enc1; W1 = wv1; bias = bv; }

    GemmCtx cx;
    gemm_setup(cx, (uint)__cvta_generic_to_shared(smg), tid, lane,
               A1, m0, W1, (size_t)head * EMB, DH, 0);

    float acc[2][4][4] = {};
    gemm_mainloop(cx, acc, wm, wn);

#pragma unroll
    for (int i = 0; i < 2; i++) {
        const int r0 = m0 + wm * 32 + 16 * i + g;
        const int r1 = r0 + 8;
#pragma unroll
        for (int j = 0; j < 4; j++) {
            const int d = wn * 32 + 8 * j + 2 * tig;
            float v00 = acc[i][j][0] + bias[head * DH + d];
            float v01 = acc[i][j][1] + bias[head * DH + d + 1];
            float v10 = acc[i][j][2] + bias[head * DH + d];
            float v11 = acc[i][j][3] + bias[head * DH + d + 1];
            if (z == 0) { v00 *= QSCALE; v01 *= QSCALE; v10 *= QSCALE; v11 *= QSCALE; }

            const int b0_ = r0 >> 11, q0_ = r0 & 2047;
            const int b1_ = r1 >> 11, q1_ = r1 & 2047;
            if (z < 2) {
                hf* O = z ? Kf : Qf;
                size_t i0 = (((size_t)b0_ * NH + head) * SEQ + q0_) * DH + d;
                *(uint*)(O + i0) = pack_h2(v00, v01);
                size_t i1 = (((size_t)b1_ * NH + head) * SEQ + q1_) * DH + d;
                *(uint*)(O + i1) = pack_h2(v10, v11);
            } else {
                size_t base0 = (((size_t)b0_ * NH + head) * DH + d) * SEQ;
                size_t base1 = (((size_t)b1_ * NH + head) * DH + d) * SEQ;
                Vtf[base0 + q0_]       = __float2half_rn(v00);
                Vtf[base0 + SEQ + q0_] = __float2half_rn(v01);
                Vtf[base1 + q1_]       = __float2half_rn(v10);
                Vtf[base1 + SEQ + q1_] = __float2half_rn(v11);
            }
        }
    }
}

// ---- output projection: grid (16 n-blocks, 32 m-blocks) ----
__global__ void __launch_bounds__(256, 3) wo_gemm(
    const hf* __restrict__ A1, const hf* __restrict__ W1,
    const float* __restrict__ bias, float* __restrict__ Of)
{
    extern __shared__ hf smg[];
    const int n0 = blockIdx.x * 64;
    const int m0 = blockIdx.y * 128;
    const int tid = threadIdx.x;
    const int lane = tid & 31, wid = tid >> 5;
    const int wm = wid & 3, wn = wid >> 2;
    const int g = lane >> 2, tig = lane & 3;

    GemmCtx cx;
    gemm_setup(cx, (uint)__cvta_generic_to_shared(smg), tid, lane,
               A1, m0, W1, 0, EMB, n0);

    float acc[2][4][4] = {};
    gemm_mainloop(cx, acc, wm, wn);

#pragma unroll
    for (int i = 0; i < 2; i++) {
        const int r0 = m0 + wm * 32 + 16 * i + g;
        const int r1 = r0 + 8;
#pragma unroll
        for (int j = 0; j < 4; j++) {
            const int c = n0 + wn * 32 + 8 * j + 2 * tig;
            Of[(size_t)r0 * EMB + c]     = acc[i][j][0] + bias[c];
            Of[(size_t)r0 * EMB + c + 1] = acc[i][j][1] + bias[c + 1];
            Of[(size_t)r1 * EMB + c]     = acc[i][j][2] + bias[c];
            Of[(size_t)r1 * EMB + c + 1] = acc[i][j][3] + bias[c + 1];
        }
    }
}

// ---------------------------------------------------------------------------
// Flash attention (round-12 version, unchanged): single fp16, Q in smem,
// K/V 2-stage cp.async ring, fp32 ex2 softmax, single-plane ctx output.
// ---------------------------------------------------------------------------
#define ST 72
#define QPLB (128 * ST * 2)      // 18432 B Q plane
#define KVPLB (64 * ST * 2)      // 9216 B per K/V plane
#define STAGEB (2 * KVPLB)       // 18432 B per stage
#define ASMEM (QPLB + 2 * STAGEB)  // 55296 B

__global__ void __launch_bounds__(256, 3) attn_mma(
    const hf* __restrict__ Qf, const hf* __restrict__ Kf,
    const hf* __restrict__ Vtf,
    hf* __restrict__ Cf)
{
    extern __shared__ hf sm[];

    const int bh = blockIdx.y;
    const int q0 = blockIdx.x * 128;
    const int tid = threadIdx.x;
    const int lane = tid & 31, wid = tid >> 5;
    const int g = lane >> 2, tig = lane & 3;

    const size_t qkbase = (size_t)bh * SEQ * DH;
    const uint smb = (uint)__cvta_generic_to_shared(sm);

    const uint a_off = (uint)(((lane & 7) + 8 * ((lane >> 3) & 1)) * (ST * 2))
                     + (uint)((lane >> 4) * 16);
    const uint b_off = (uint)(((lane & 7) + 8 * (lane >> 4)) * (ST * 2))
                     + (uint)(((lane >> 3) & 1) * 16);
    const uint q_stat = smb + a_off + (uint)(wid * 16 * ST * 2);
    const uint k_stat = smb + QPLB + b_off;
    const uint v_stat = k_stat + KVPLB;

    const int krow = tid >> 3, kch = tid & 7;
    const hf* kp = Kf + qkbase + (size_t)krow * DH + kch * 8;
    const hf* vp = Vtf + ((size_t)bh * DH + krow) * SEQ + kch * 8;
    const uint kd = smb + QPLB + (uint)((krow * ST + kch * 8) * 2);
    const uint vd = kd + KVPLB;

    {
        const hf* qs = Qf + qkbase + (size_t)(q0 + (tid >> 1)) * DH + (tid & 1) * 32;
        const uint qd = smb + (uint)(((tid >> 1) * ST + (tid & 1) * 32) * 2);
#pragma unroll
        for (int c = 0; c < 4; c++) cp_async16(qd + c * 16, qs + c * 8);
    }
    cp_async16(kd, kp);                       cp_async16(kd + 32 * ST * 2, kp + 32 * DH);
    cp_async16(vd, vp);                       cp_async16(vd + 32 * ST * 2, vp + 32 * SEQ);
    CP_COMMIT();
    cp_async16(kd + STAGEB, kp + 64 * DH);    cp_async16(kd + STAGEB + 32 * ST * 2, kp + 96 * DH);
    cp_async16(vd + STAGEB, vp + 64);         cp_async16(vd + STAGEB + 32 * ST * 2, vp + 64 + 32 * SEQ);
    CP_COMMIT();

    float l0 = 0.f, l1 = 0.f;
    float o[8][4] = {};

#pragma unroll 1
    for (int t = 0; t < 32; t++) {
        const uint so = (uint)((t & 1) * STAGEB);

        CP_WAIT1();
        __syncthreads();

        float s[8][4] = {};
#pragma unroll
        for (int kk = 0; kk < 4; kk++) {
            uint qa0, qa1, qa2, qa3;
            LDSM4(qa0, qa1, qa2, qa3, q_stat + (uint)(kk * 32));
#pragma unroll
            for (int jp = 0; jp < 4; jp++) {
                uint r0, r1, r2, r3;
                LDSM4(r0, r1, r2, r3, k_stat + so + (uint)(jp * 16 * ST * 2 + kk * 32));
                MMA_F16(s[2 * jp],     qa0, qa1, qa2, qa3, r0, r1);
                MMA_F16(s[2 * jp + 1], qa0, qa1, qa2, qa3, r2, r3);
            }
        }

#pragma unroll
        for (int kk = 0; kk < 4; kk++) {
            const int j0 = 2 * kk, j1 = 2 * kk + 1;
            float p00 = fast_ex2(s[j0][0]), p01 = fast_ex2(s[j0][1]);
            float p02 = fast_ex2(s[j0][2]), p03 = fast_ex2(s[j0][3]);
            float p10 = fast_ex2(s[j1][0]), p11 = fast_ex2(s[j1][1]);
            float p12 = fast_ex2(s[j1][2]), p13 = fast_ex2(s[j1][3]);
            l0 += p00 + p01 + p10 + p11;
            l1 += p02 + p03 + p12 + p13;
            const uint pa0 = pack_h2(p00, p01);
            const uint pa1 = pack_h2(p02, p03);
            const uint pa2 = pack_h2(p10, p11);
            const uint pa3 = pack_h2(p12, p13);
#pragma unroll
            for (int jp = 0; jp < 4; jp++) {
                uint r0, r1, r2, r3;
                LDSM4(r0, r1, r2, r3, v_stat + so + (uint)(jp * 16 * ST * 2 + kk * 32));
                MMA_F16(o[2 * jp],     pa0, pa1, pa2, pa3, r0, r1);
                MMA_F16(o[2 * jp + 1], pa0, pa1, pa2, pa3, r2, r3);
            }
        }

        __syncthreads();

        if (t + 2 < 32) {
            const uint sd = (uint)((t & 1) * STAGEB);
            const hf* ks = kp + (size_t)(t + 2) * 64 * DH;
            const hf* vs = vp + (t + 2) * 64;
            cp_async16(kd + sd, ks);
            cp_async16(kd + sd + 32 * ST * 2, ks + 32 * DH);
            cp_async16(vd + sd, vs);
            cp_async16(vd + sd + 32 * ST * 2, vs + 32 * SEQ);
        }
        CP_COMMIT();
    }

    l0 += __shfl_xor_sync(0xffffffffu, l0, 1);
    l0 += __shfl_xor_sync(0xffffffffu, l0, 2);
    l1 += __shfl_xor_sync(0xffffffffu, l1, 1);
    l1 += __shfl_xor_sync(0xffffffffu, l1, 2);
    const float inv0 = 1.0f / l0, inv1 = 1.0f / l1;

    const int b = bh >> 4, h = bh & 15;
    const int row0 = q0 + wid * 16 + g;
    const size_t m0g = (size_t)b * SEQ + row0;
    const size_t m1g = m0g + 8;
#pragma unroll
    for (int j = 0; j < 8; j++) {
        const int col = h * 64 + 8 * j + 2 * tig;
        *(uint*)(Cf + m0g * EMB + col) = pack_h2(o[j][0] * inv0, o[j][1] * inv0);
        *(uint*)(Cf + m1g * EMB + col) = pack_h2(o[j][2] * inv1, o[j][3] * inv1);
    }
}

// ---------------------------------------------------------------------------
extern "C" void kernel_launch(void* const* d_in, const int* in_sizes, int n_in,
                              void* d_out, int out_size)
{
    const float* dec = (const float*)d_in[0];
    const float* enc = (const float*)d_in[1];
    const float* wq  = (const float*)d_in[2];
    const float* bq  = (const float*)d_in[3];
    const float* wk  = (const float*)d_in[4];
    const float* bk  = (const float*)d_in[5];
    const float* wv  = (const float*)d_in[6];
    const float* bv  = (const float*)d_in[7];
    const float* wo  = (const float*)d_in[8];
    const float* bo  = (const float*)d_in[9];
    float* out = (float*)d_out;

    hf *dec1, *enc1, *wq1, *wk1, *wv1, *wo1;
    hf *qf, *kf, *vtf, *ctx1;
    cudaGetSymbolAddress((void**)&dec1, g_dec1); cudaGetSymbolAddress((void**)&enc1, g_enc1);
    cudaGetSymbolAddress((void**)&wq1, g_wq1);   cudaGetSymbolAddress((void**)&wk1, g_wk1);
    cudaGetSymbolAddress((void**)&wv1, g_wv1);   cudaGetSymbolAddress((void**)&wo1, g_wo1);
    cudaGetSymbolAddress((void**)&qf, g_Qf);     cudaGetSymbolAddress((void**)&kf, g_Kf);
    cudaGetSymbolAddress((void**)&vtf, g_Vtf);   cudaGetSymbolAddress((void**)&ctx1, g_ctx1);

    cudaFuncSetAttribute(attn_mma, cudaFuncAttributeMaxDynamicSharedMemorySize, ASMEM);
    cudaFuncSetAttribute(qkv_gemm, cudaFuncAttributeMaxDynamicSharedMemorySize, GSMEM);
    cudaFuncSetAttribute(wo_gemm,  cudaFuncAttributeMaxDynamicSharedMemorySize, GSMEM);

    // 1) fp32 -> fp16 converts
    const int nAct = MTOT * EMB;
    const int nW   = EMB * EMB;
    dim3 gduo(nAct / 512, 2);
    conv_duo<<<gduo, 256>>>(dec, dec1, enc, enc1, nAct);
    dim3 gquad(nW / 512, 4);
    conv_quad<<<gquad, 256>>>(wq, wq1, wk, wk1, wv, wv1, wo, wo1, nW);

    // 2) fused QKV projections (BK=64)
    dim3 gqkv(NH, MTOT / 128, 3);
    qkv_gemm<<<gqkv, 256, GSMEM>>>(dec1, enc1, wq1, wk1, wv1,
                                   bq, bk, bv, qf, kf, vtf);

    // 3) attention
    dim3 gattn(SEQ / 128, BB * NH);
    attn_mma<<<gattn, 256, ASMEM>>>(qf, kf, vtf, ctx1);

    // 4) output projection (fp32 out, BK=64)
    dim3 gwo(EMB / 64, MTOT / 128);
    wo_gemm<<<gwo, 256, GSMEM>>>(ctx1, wo1, bo, out);
}